// round 14
// baseline (speedup 1.0000x reference)
#include <cuda_runtime.h>
#include <cuda_bf16.h>
#include <math.h>
#include <stdint.h>

#define B_   4
#define T_   2048
#define D_   2048
#define NH   16
#define NKV  4
#define HD   128
#define KVD  (NKV*HD)      // 512
#define NQKV (D_ + 2*KVD)  // 3072
#define KW   (2*D_)        // 4096: [hi|lo] 2-plane operand width

// 1/sqrt(hd) * log2(e), folded into Q split
#define SCALE_LOG2E 0.1275174277208884f

// ---------------- scratch (__device__ globals; allocation-free rule) -------
__device__ float g_QKV[(size_t)B_ * T_ * NQKV];          // fused projection out

__device__ __nv_bfloat16 g_AE   [(size_t)(B_*T_) * KW];  // x-expand / attn-out-expand
__device__ __nv_bfloat16 g_WQKVE[(size_t)NQKV * KW];     // Wq|Wk|Wv expanded [hi|lo]
__device__ __nv_bfloat16 g_WOE  [(size_t)D_   * KW];

// attention split operands: [Qh|Ql], [Kh|Kl] (256 cols each)
__device__ __nv_bfloat16 g_Qe [(size_t)B_ * NH  * T_ * 256];
__device__ __nv_bfloat16 g_Ke [(size_t)B_ * NKV * T_ * 256];
__device__ __nv_bfloat16 g_Vth[(size_t)B_ * NKV * HD * T_];   // [b,kvh,d,t] hi
__device__ __nv_bfloat16 g_Vtl[(size_t)B_ * NKV * HD * T_];   // lo

// ---------------- helpers --------------------------------------------------
__device__ __forceinline__ uint32_t smem_u32(const void* p) {
    uint32_t a;
    asm("{ .reg .u64 t; cvta.to.shared.u64 t, %1; cvt.u32.u64 %0, t; }" : "=r"(a) : "l"(p));
    return a;
}
#define CP_ASYNC16(dst, src) \
    asm volatile("cp.async.cg.shared.global [%0], [%1], 16;" :: "r"(dst), "l"(src) : "memory")
#define CP_COMMIT() asm volatile("cp.async.commit_group;" ::: "memory")
#define CP_WAIT(N)  asm volatile("cp.async.wait_group %0;" :: "n"(N) : "memory")

#define LDMATRIX_X4(r0, r1, r2, r3, addr) \
    asm volatile("ldmatrix.sync.aligned.m8n8.x4.shared.b16 {%0,%1,%2,%3}, [%4];" \
        : "=r"(r0), "=r"(r1), "=r"(r2), "=r"(r3) : "r"(addr))

#define MMA_BF16(d, a, b0, b1) \
    asm volatile("mma.sync.aligned.m16n8k16.row.col.f32.bf16.bf16.f32 " \
        "{%0,%1,%2,%3}, {%4,%5,%6,%7}, {%8,%9}, {%0,%1,%2,%3};" \
        : "+f"((d)[0]), "+f"((d)[1]), "+f"((d)[2]), "+f"((d)[3]) \
        : "r"((a)[0]), "r"((a)[1]), "r"((a)[2]), "r"((a)[3]), "r"(b0), "r"(b1))

// pack two fp32 into bf16x2 (lo -> low half, hi -> high half)
__device__ __forceinline__ uint32_t packbf2(float lo, float hi) {
    uint32_t r;
    asm("cvt.rn.bf16x2.f32 %0, %1, %2;" : "=r"(r) : "f"(hi), "f"(lo));
    return r;
}

// ---------------------------------------------------------------------------
// split conversion: fp32 [M,K] -> bf16 [M,2K] = [hi plane | lo plane]
// ---------------------------------------------------------------------------
__global__ void split2_kernel(const float* __restrict__ in, __nv_bfloat16* __restrict__ out,
                              int K, size_t total)
{
    for (size_t e = (size_t)blockIdx.x * blockDim.x + threadIdx.x; e < total;
         e += (size_t)gridDim.x * blockDim.x) {
        size_t m = e / (size_t)K;
        int k = (int)(e - m * (size_t)K);
        float v = in[e];
        __nv_bfloat16 hi = __float2bfloat16(v);
        __nv_bfloat16* row = out + m * (size_t)(2 * K);
        row[k]     = hi;
        row[K + k] = __float2bfloat16(v - __bfloat162float(hi));
    }
}

// Fused weight split: Wq|Wk|Wv -> WQKVE rows, Wo -> WOE.  All K = D_.
__global__ void split2_weights_kernel(const float* __restrict__ Wq,
                                      const float* __restrict__ Wk,
                                      const float* __restrict__ Wv,
                                      const float* __restrict__ Wo)
{
    const size_t total = (size_t)(NQKV + D_) * D_;
    for (size_t e = (size_t)blockIdx.x * blockDim.x + threadIdx.x; e < total;
         e += (size_t)gridDim.x * blockDim.x) {
        size_t r = e / (size_t)D_;
        int k = (int)(e - r * (size_t)D_);
        const float* src;
        __nv_bfloat16* dst;
        if (r < D_)              { src = Wq + r * (size_t)D_ + k;
                                   dst = g_WQKVE + r * (size_t)KW; }
        else if (r < D_ + KVD)   { src = Wk + (r - D_) * (size_t)D_ + k;
                                   dst = g_WQKVE + r * (size_t)KW; }
        else if (r < NQKV)       { src = Wv + (r - D_ - KVD) * (size_t)D_ + k;
                                   dst = g_WQKVE + r * (size_t)KW; }
        else                     { src = Wo + (r - NQKV) * (size_t)D_ + k;
                                   dst = g_WOE + (r - NQKV) * (size_t)KW; }
        float v = *src;
        __nv_bfloat16 hi = __float2bfloat16(v);
        dst[k]      = hi;
        dst[D_ + k] = __float2bfloat16(v - __bfloat162float(hi));
    }
}

// ---------------------------------------------------------------------------
// Plane-reuse HMMA GEMM, 4-stage k16 pipeline.  Tile 128x128, 2 CTA/SM.
// Stage = {Ah|Al|Bh|Bl} 128x16 bf16 each, 48B padded row stride (conflict-
// free ldmatrix), 24KB/stage, 96KB total.  CP_WAIT(2): 2-3 loads in flight.
// ---------------------------------------------------------------------------
#define G4_STRIDE   48
#define G4_TILE_B   (128 * G4_STRIDE)        // 6144
#define G4_STAGE_B  (4 * G4_TILE_B)          // 24576: Ah|Al|Bh|Bl
#define GEMM4_SMEM  (4 * G4_STAGE_B)         // 98304
#define G4_NCH      (D_ / 16)                // 128 k16-groups

__global__ __launch_bounds__(256, 2)
void gemm4_bf16_nt(const __nv_bfloat16* __restrict__ A, const __nv_bfloat16* __restrict__ B,
                   float* __restrict__ C, int N)
{
    extern __shared__ char smraw[];
    const uint32_t smem = smem_u32(smraw);

    const int tid    = threadIdx.x;
    const int lane   = tid & 31;
    const int wid    = tid >> 5;
    const int warp_m = wid & 3;
    const int warp_n = wid >> 2;

    const __nv_bfloat16* Ag = A + (size_t)blockIdx.y * 128 * KW;
    const __nv_bfloat16* Bg = B + (size_t)blockIdx.x * 128 * KW;

    // per-stage load: each thread does 1 cp16 per tile (row = tid>>1, half = tid&1)
    const int l_row  = tid >> 1;
    const int l_half = tid & 1;
    auto load_stage = [&](int c, int buf) {
        const uint32_t sb  = smem + buf * G4_STAGE_B;
        const uint32_t off = (uint32_t)(l_row * G4_STRIDE + l_half * 16);
        const size_t g = (size_t)l_row * KW + c * 16 + l_half * 8;
        CP_ASYNC16(sb + 0 * G4_TILE_B + off, Ag + g);        // Ah
        CP_ASYNC16(sb + 1 * G4_TILE_B + off, Ag + g + D_);   // Al
        CP_ASYNC16(sb + 2 * G4_TILE_B + off, Bg + g);        // Bh
        CP_ASYNC16(sb + 3 * G4_TILE_B + off, Bg + g + D_);   // Bl
        CP_COMMIT();
    };

    float acc[2][8][4];
#pragma unroll
    for (int t = 0; t < 2; t++)
#pragma unroll
        for (int n = 0; n < 8; n++)
#pragma unroll
            for (int x = 0; x < 4; x++) acc[t][n][x] = 0.f;

    load_stage(0, 0);
    load_stage(1, 1);
    load_stage(2, 2);

    const uint32_t lm_row = (uint32_t)((lane & 15) * G4_STRIDE + (lane >> 4) * 16);
    const uint32_t a_off  = (uint32_t)(warp_m * 32 * G4_STRIDE) + lm_row;
    const uint32_t b_off  = (uint32_t)(warp_n * 64 * G4_STRIDE) + lm_row;

    for (int c = 0; c < G4_NCH; c++) {
        CP_WAIT(2);
        __syncthreads();
        if (c + 3 < G4_NCH) load_stage(c + 3, (c + 3) & 3); else CP_COMMIT();

        const uint32_t st  = smem + (c & 3) * G4_STAGE_B;
        uint32_t ah[2][4], bh[4][4];
#pragma unroll
        for (int t = 0; t < 2; t++)
            LDMATRIX_X4(ah[t][0], ah[t][1], ah[t][2], ah[t][3],
                        st + 0 * G4_TILE_B + a_off + (uint32_t)(t * 16 * G4_STRIDE));
#pragma unroll
        for (int p = 0; p < 4; p++)
            LDMATRIX_X4(bh[p][0], bh[p][1], bh[p][2], bh[p][3],
                        st + 2 * G4_TILE_B + b_off + (uint32_t)(p * 16 * G4_STRIDE));
        // Ah x Bh
#pragma unroll
        for (int t = 0; t < 2; t++)
#pragma unroll
            for (int p = 0; p < 4; p++) {
                MMA_BF16(acc[t][2 * p],     ah[t], bh[p][0], bh[p][2]);
                MMA_BF16(acc[t][2 * p + 1], ah[t], bh[p][1], bh[p][3]);
            }
        // Al x Bh (Bh frags reused)
        {
            uint32_t al[2][4];
#pragma unroll
            for (int t = 0; t < 2; t++)
                LDMATRIX_X4(al[t][0], al[t][1], al[t][2], al[t][3],
                            st + 1 * G4_TILE_B + a_off + (uint32_t)(t * 16 * G4_STRIDE));
#pragma unroll
            for (int t = 0; t < 2; t++)
#pragma unroll
                for (int p = 0; p < 4; p++) {
                    MMA_BF16(acc[t][2 * p],     al[t], bh[p][0], bh[p][2]);
                    MMA_BF16(acc[t][2 * p + 1], al[t], bh[p][1], bh[p][3]);
                }
        }
        // Ah x Bl (Ah frags reused)
        {
            uint32_t bl[4][4];
#pragma unroll
            for (int p = 0; p < 4; p++)
                LDMATRIX_X4(bl[p][0], bl[p][1], bl[p][2], bl[p][3],
                            st + 3 * G4_TILE_B + b_off + (uint32_t)(p * 16 * G4_STRIDE));
#pragma unroll
            for (int t = 0; t < 2; t++)
#pragma unroll
                for (int p = 0; p < 4; p++) {
                    MMA_BF16(acc[t][2 * p],     ah[t], bl[p][0], bl[p][2]);
                    MMA_BF16(acc[t][2 * p + 1], ah[t], bl[p][1], bl[p][3]);
                }
        }
    }

#pragma unroll
    for (int t = 0; t < 2; t++) {
        const int row0 = blockIdx.y * 128 + warp_m * 32 + t * 16 + (lane >> 2);
#pragma unroll
        for (int n = 0; n < 8; n++) {
            const int col = blockIdx.x * 128 + warp_n * 64 + n * 8 + (lane & 3) * 2;
            *(float2*)(C + (size_t)row0 * N + col) =
                make_float2(acc[t][n][0], acc[t][n][1]);
            *(float2*)(C + (size_t)(row0 + 8) * N + col) =
                make_float2(acc[t][n][2], acc[t][n][3]);
        }
    }
}

// ---------------------------------------------------------------------------
// RoPE + hi/lo split (unchanged)
// ---------------------------------------------------------------------------
__global__ void rope_split_kernel()
{
    const int t = blockIdx.x;
    const int b = blockIdx.y;
    const float LOG2_10000_OVER_64 = 0.20762050593045952f;
    const float* base = g_QKV + (size_t)(b * T_ + t) * NQKV;

    for (int idx = threadIdx.x; idx < NH * 64; idx += blockDim.x) {
        const int head = idx >> 6;
        const int i    = idx & 63;
        const float invf = exp2f(-(float)i * LOG2_10000_OVER_64);
        float s, c;
        sincosf((float)t * invf, &s, &c);
        const float* p = base + head * HD;
        float q1 = p[i], q2 = p[i + 64];
        float r1 = (q1 * c - q2 * s) * SCALE_LOG2E;
        float r2 = (q1 * s + q2 * c) * SCALE_LOG2E;
        __nv_bfloat16 h1 = __float2bfloat16(r1);
        __nv_bfloat16 h2 = __float2bfloat16(r2);
        __nv_bfloat16* row = g_Qe + ((size_t)(b * NH + head) * T_ + t) * 256;
        row[i]       = h1;  row[i + 64]  = h2;
        row[128 + i] = __float2bfloat16(r1 - __bfloat162float(h1));
        row[192 + i] = __float2bfloat16(r2 - __bfloat162float(h2));
    }
    for (int idx = threadIdx.x; idx < NKV * 64; idx += blockDim.x) {
        const int kvh = idx >> 6;
        const int i   = idx & 63;
        const float invf = exp2f(-(float)i * LOG2_10000_OVER_64);
        float s, c;
        sincosf((float)t * invf, &s, &c);
        const float* p = base + D_ + kvh * HD;
        float q1 = p[i], q2 = p[i + 64];
        float r1 = q1 * c - q2 * s;
        float r2 = q1 * s + q2 * c;
        __nv_bfloat16 h1 = __float2bfloat16(r1);
        __nv_bfloat16 h2 = __float2bfloat16(r2);
        __nv_bfloat16* row = g_Ke + ((size_t)(b * NKV + kvh) * T_ + t) * 256;
        row[i]       = h1;  row[i + 64]  = h2;
        row[128 + i] = __float2bfloat16(r1 - __bfloat162float(h1));
        row[192 + i] = __float2bfloat16(r2 - __bfloat162float(h2));
    }
}

// V transpose + split (unchanged)
__global__ void v_split_kernel()   // grid (T_/32, B_*NKV), 256 thr
{
    __shared__ float ts[32][129];
    const int t0 = blockIdx.x * 32;
    const int bz = blockIdx.y;
    const int b = bz >> 2, kvh = bz & 3;
    const float* src = g_QKV + (size_t)(b * T_ + t0) * NQKV + D_ + KVD + kvh * HD;
#pragma unroll
    for (int k = 0; k < 16; k++) {
        const int idx = threadIdx.x + k * 256;
        const int d = idx & 127, t = idx >> 7;
        ts[t][d] = src[(size_t)t * NQKV + d];
    }
    __syncthreads();
    __nv_bfloat16* dh = g_Vth + (size_t)bz * HD * T_ + t0;
    __nv_bfloat16* dl = g_Vtl + (size_t)bz * HD * T_ + t0;
#pragma unroll
    for (int k = 0; k < 16; k++) {
        const int idx = threadIdx.x + k * 256;
        const int t = idx & 31, d = idx >> 5;
        const float v = ts[t][d];
        __nv_bfloat16 hi = __float2bfloat16(v);
        dh[(size_t)d * T_ + t] = hi;
        dl[(size_t)d * T_ + t] = __float2bfloat16(v - __bfloat162float(hi));
    }
}

// ---------------------------------------------------------------------------
// HMMA flash attention with register-resident P (unchanged from R13)
// ---------------------------------------------------------------------------
#define AT_QROWB 528
#define AT_CH_B  18432
#define SQ_OFF   0
#define SKV_OFF  (128 * AT_QROWB)                  // 67584
#define ATT_SMEM (SKV_OFF + 4 * AT_CH_B)           // 141312

__global__ __launch_bounds__(256, 1) void attn_mma()
{
    extern __shared__ char smraw[];
    const uint32_t sb0 = smem_u32(smraw);

    const int tid  = threadIdx.x;
    const int lane = tid & 31;
    const int w    = tid >> 5;
    const int qi   = 15 - (int)blockIdx.x;
    const int h    = blockIdx.y;
    const int b    = blockIdx.z;
    const int kvh  = h >> 2;

    const __nv_bfloat16* Qg  = g_Qe + ((size_t)(b * NH + h) * T_ + qi * 128) * 256;
    const __nv_bfloat16* Kg  = g_Ke + ((size_t)(b * NKV + kvh) * T_) * 256;
    const __nv_bfloat16* Vhg = g_Vth + (size_t)(b * NKV + kvh) * HD * T_;
    const __nv_bfloat16* Vlg = g_Vtl + (size_t)(b * NKV + kvh) * HD * T_;

    {
        const int row = tid >> 1, half = tid & 1;
#pragma unroll
        for (int jj = 0; jj < 16; jj++) {
            const int c16 = half * 16 + jj;
            CP_ASYNC16(sb0 + SQ_OFF + (uint32_t)(row * AT_QROWB + c16 * 16),
                       Qg + (size_t)row * 256 + c16 * 8);
        }
        CP_COMMIT();
    }

    auto load_k = [&](int j, int c, int st) {
#pragma unroll
        for (int jj = 0; jj < 4; jj++) {
            const int p   = tid + (jj << 8);
            const int row = p >> 3;
            const int c16 = p & 7;
            CP_ASYNC16(sb0 + SKV_OFF + st * AT_CH_B + (uint32_t)(row * 144 + c16 * 16),
                       Kg + (size_t)(j * 128 + row) * 256 + c * 64 + c16 * 8);
        }
        CP_COMMIT();
    };
    auto load_v = [&](int j, int c, int st) {
        const __nv_bfloat16* Vg = (c < 2) ? Vhg : Vlg;
        const int toff = j * 128 + (c & 1) * 64;
#pragma unroll
        for (int jj = 0; jj < 4; jj++) {
            const int p   = tid + (jj << 8);
            const int row = p >> 3;
            const int c16 = p & 7;
            CP_ASYNC16(sb0 + SKV_OFF + st * AT_CH_B + (uint32_t)(row * 144 + c16 * 16),
                       Vg + (size_t)row * T_ + toff + c16 * 8);
        }
        CP_COMMIT();
    };

    float o[16][4];
#pragma unroll
    for (int n = 0; n < 16; n++)
#pragma unroll
        for (int x = 0; x < 4; x++) o[n][x] = 0.f;
    float m0 = -1e30f, m1 = -1e30f, l0 = 0.f, l1 = 0.f;

    const uint32_t lm144   = (uint32_t)((lane & 15) * 144 + (lane >> 4) * 16);
    const uint32_t aq_base = sb0 + SQ_OFF + (uint32_t)((w * 16 + (lane & 15)) * AT_QROWB + (lane >> 4) * 16);
    const int rloc0 = w * 16 + (lane >> 2);
    const int cbase = (lane & 3) * 2;

    load_k(0, 0, 0); load_k(0, 1, 1); load_k(0, 2, 2); load_k(0, 3, 3);

    for (int j = 0; j <= qi; j++) {
        float s[16][4];
#pragma unroll
        for (int n = 0; n < 16; n++)
#pragma unroll
            for (int x = 0; x < 4; x++) s[n][x] = 0.f;

        // ================= QK phase (V(j) prefetch interleaved) ===========
#pragma unroll
        for (int c = 0; c < 4; c++) {
            if (c == 0) { CP_WAIT(3); } else { CP_WAIT(2); }
            __syncthreads();
            if (c >= 1) load_v(j, c - 1, c - 1);

            const uint32_t sbK = sb0 + SKV_OFF + c * AT_CH_B;
            const uint32_t qsl = (uint32_t)((c & 1) * 128);
#pragma unroll
            for (int ks = 0; ks < 4; ks++) {
                const uint32_t ko = (uint32_t)(ks * 32);
                uint32_t bfr[8][4];
#pragma unroll
                for (int p = 0; p < 8; p++)
                    LDMATRIX_X4(bfr[p][0], bfr[p][1], bfr[p][2], bfr[p][3],
                                sbK + (uint32_t)(p * 16 * 144) + lm144 + ko);
                uint32_t af[4];
                LDMATRIX_X4(af[0], af[1], af[2], af[3], aq_base + qsl + ko);
#pragma unroll
                for (int p = 0; p < 8; p++) {
                    MMA_BF16(s[2 * p],     af, bfr[p][0], bfr[p][2]);
                    MMA_BF16(s[2 * p + 1], af, bfr[p][1], bfr[p][3]);
                }
                if (c < 2) {
                    uint32_t ag[4];
                    LDMATRIX_X4(ag[0], ag[1], ag[2], ag[3], aq_base + qsl + 256u + ko);
#pragma unroll
                    for (int p = 0; p < 8; p++) {
                        MMA_BF16(s[2 * p],     ag, bfr[p][0], bfr[p][2]);
                        MMA_BF16(s[2 * p + 1], ag, bfr[p][1], bfr[p][3]);
                    }
                }
            }
        }
        __syncthreads();
        load_v(j, 3, 3);

        // ---- causal mask (diagonal block) ----
        if (j == qi) {
#pragma unroll
            for (int n = 0; n < 16; n++) {
                const int col = n * 8 + cbase;
#pragma unroll
                for (int x = 0; x < 4; x++) {
                    const int cc = col + (x & 1);
                    const int rr = rloc0 + ((x >> 1) << 3);
                    if (cc > rr) s[n][x] = -1e30f;
                }
            }
        }

        // ---- online softmax; pack P fragments in registers ----
        float mx0 = -1e30f, mx1 = -1e30f;
#pragma unroll
        for (int n = 0; n < 16; n++) {
            mx0 = fmaxf(mx0, fmaxf(s[n][0], s[n][1]));
            mx1 = fmaxf(mx1, fmaxf(s[n][2], s[n][3]));
        }
        mx0 = fmaxf(mx0, __shfl_xor_sync(0xffffffffu, mx0, 1));
        mx0 = fmaxf(mx0, __shfl_xor_sync(0xffffffffu, mx0, 2));
        mx1 = fmaxf(mx1, __shfl_xor_sync(0xffffffffu, mx1, 1));
        mx1 = fmaxf(mx1, __shfl_xor_sync(0xffffffffu, mx1, 2));

        const float mn0 = fmaxf(m0, mx0), mn1 = fmaxf(m1, mx1);
        const float a0 = exp2f(m0 - mn0), a1 = exp2f(m1 - mn1);
        m0 = mn0; m1 = mn1;

        uint32_t ph[8][4], pl[8][4];
        float sum0 = 0.f, sum1 = 0.f;
#pragma unroll
        for (int i = 0; i < 8; i++) {
            float p00 = exp2f(s[2*i][0]   - mn0), p01 = exp2f(s[2*i][1]   - mn0);
            float p02 = exp2f(s[2*i][2]   - mn1), p03 = exp2f(s[2*i][3]   - mn1);
            float p10 = exp2f(s[2*i+1][0] - mn0), p11 = exp2f(s[2*i+1][1] - mn0);
            float p12 = exp2f(s[2*i+1][2] - mn1), p13 = exp2f(s[2*i+1][3] - mn1);
            sum0 += p00 + p01 + p10 + p11;
            sum1 += p02 + p03 + p12 + p13;
            ph[i][0] = packbf2(p00, p01);
            ph[i][1] = packbf2(p02, p03);
            ph[i][2] = packbf2(p10, p11);
            ph[i][3] = packbf2(p12, p13);
            __nv_bfloat162 h0 = *(__nv_bfloat162*)&ph[i][0];
            __nv_bfloat162 h1 = *(__nv_bfloat162*)&ph[i][1];
            __nv_bfloat162 h2 = *(__nv_bfloat162*)&ph[i][2];
            __nv_bfloat162 h3 = *(__nv_bfloat162*)&ph[i][3];
            pl[i][0] = packbf2(p00 - __bfloat162float(h0.x), p01 - __bfloat162float(h0.y));
            pl[i][1] = packbf2(p02 - __bfloat162float(h1.x), p03 - __bfloat162float(h1.y));
            pl[i][2] = packbf2(p10 - __bfloat162float(h2.x), p11 - __bfloat162float(h2.y));
            pl[i][3] = packbf2(p12 - __bfloat162float(h3.x), p13 - __bfloat162float(h3.y));
        }
        sum0 += __shfl_xor_sync(0xffffffffu, sum0, 1);
        sum0 += __shfl_xor_sync(0xffffffffu, sum0, 2);
        sum1 += __shfl_xor_sync(0xffffffffu, sum1, 1);
        sum1 += __shfl_xor_sync(0xffffffffu, sum1, 2);
        l0 = l0 * a0 + sum0;
        l1 = l1 * a1 + sum1;

#pragma unroll
        for (int n = 0; n < 16; n++) {
            o[n][0] *= a0; o[n][1] *= a0; o[n][2] *= a1; o[n][3] *= a1;
        }

        // ================= PV phase (K(j+1) prefetch interleaved) =========
        const bool more = (j < qi);
#pragma unroll
        for (int c = 0; c < 4; c++) {
            if (c == 0) { CP_WAIT(3); } else { CP_WAIT(2); }
            __syncthreads();
            if (c >= 1) { if (more) load_k(j + 1, c - 1, c - 1); else CP_COMMIT(); }

            const uint32_t sbV = sb0 + SKV_OFF + c * AT_CH_B;
            const int ib = (c & 1) * 4;
#pragma unroll
            for (int ks = 0; ks < 4; ks++) {
                uint32_t bfr[8][4];
#pragma unroll
                for (int p = 0; p < 8; p++)
                    LDMATRIX_X4(bfr[p][0], bfr[p][1], bfr[p][2], bfr[p][3],
                                sbV + (uint32_t)(p * 16 * 144) + lm144 + (uint32_t)(ks * 32));
                const int i = ib + ks;
#pragma unroll
                for (int p = 0; p < 8; p++) {
                    MMA_BF16(o[2 * p],     ph[i], bfr[p][0], bfr[p][2]);
                    MMA_BF16(o[2 * p + 1], ph[i], bfr[p][1], bfr[p][3]);
                }
                if (c < 2) {
#pragma unroll
                    for (int p = 0; p < 8; p++) {
                        MMA_BF16(o[2 * p],     pl[i], bfr[p][0], bfr[p][2]);
                        MMA_BF16(o[2 * p + 1], pl[i], bfr[p][1], bfr[p][3]);
                    }
                }
            }
        }
        __syncthreads();
        if (more) load_k(j + 1, 3, 3); else CP_COMMIT();
    }

    // ---- epilogue: normalize + [hi|lo] split straight into g_AE ----
    const float il0 = 1.f / l0, il1 = 1.f / l1;
    const int grow0 = qi * 128 + rloc0;
    __nv_bfloat16* r0 = g_AE + (size_t)(b * T_ + grow0) * KW;
    __nv_bfloat16* r1 = g_AE + (size_t)(b * T_ + grow0 + 8) * KW;
#pragma unroll
    for (int n = 0; n < 16; n++) {
        const int col = h * HD + n * 8 + cbase;
        float v0 = o[n][0] * il0, v1 = o[n][1] * il0;
        float v2 = o[n][2] * il1, v3 = o[n][3] * il1;
        __nv_bfloat16 a = __float2bfloat16(v0), bb = __float2bfloat16(v1);
        __nv_bfloat16 cc = __float2bfloat16(v2), dd = __float2bfloat16(v3);
        *(__nv_bfloat162*)(r0 + col)      = __nv_bfloat162(a, bb);
        *(__nv_bfloat162*)(r0 + D_ + col) =
            __nv_bfloat162(__float2bfloat16(v0 - __bfloat162float(a)),
                           __float2bfloat16(v1 - __bfloat162float(bb)));
        *(__nv_bfloat162*)(r1 + col)      = __nv_bfloat162(cc, dd);
        *(__nv_bfloat162*)(r1 + D_ + col) =
            __nv_bfloat162(__float2bfloat16(v2 - __bfloat162float(cc)),
                           __float2bfloat16(v3 - __bfloat162float(dd)));
    }
}

// ---------------------------------------------------------------------------
extern "C" void kernel_launch(void* const* d_in, const int* in_sizes, int n_in,
                              void* d_out, int out_size)
{
    const float* x  = (const float*)d_in[0];
    const float* Wq = (const float*)d_in[1];
    const float* Wk = (const float*)d_in[2];
    const float* Wv = (const float*)d_in[3];
    const float* Wo = (const float*)d_in[4];
    float* out = (float*)d_out;

    float* QKVb;
    __nv_bfloat16 *AE, *WQKVE, *WOE;
    cudaGetSymbolAddress((void**)&QKVb, g_QKV);
    cudaGetSymbolAddress((void**)&AE, g_AE);
    cudaGetSymbolAddress((void**)&WQKVE, g_WQKVE);
    cudaGetSymbolAddress((void**)&WOE, g_WOE);

    const int M = B_ * T_;  // 8192

    cudaFuncSetAttribute(gemm4_bf16_nt, cudaFuncAttributeMaxDynamicSharedMemorySize,
                         GEMM4_SMEM);
    cudaFuncSetAttribute(attn_mma, cudaFuncAttributeMaxDynamicSharedMemorySize,
                         ATT_SMEM);

    // split conversions: x + all four weights (fused)
    split2_kernel<<<4096, 256>>>(x, AE, D_, (size_t)M * D_);
    split2_weights_kernel<<<4096, 256>>>(Wq, Wk, Wv, Wo);

    // fused QKV projection (plane-reuse GEMM, 4-stage k16, 2 CTA/SM)
    gemm4_bf16_nt<<<dim3(NQKV / 128, M / 128), 256, GEMM4_SMEM>>>(AE, WQKVE, QKVb, NQKV);

    // attention operand prep
    rope_split_kernel<<<dim3(T_, B_), 256>>>();
    v_split_kernel<<<dim3(T_ / 32, B_ * NKV), 256>>>();

    // tensor-core flash attention (register-resident P; writes [hi|lo] into AE)
    attn_mma<<<dim3(T_ / 128, NH, B_), 256, ATT_SMEM>>>();

    // output projection
    gemm4_bf16_nt<<<dim3(D_ / 128, M / 128), 256, GEMM4_SMEM>>>(AE, WOE, out, D_);
}

// round 15
// speedup vs baseline: 1.1070x; 1.1070x over previous
#include <cuda_runtime.h>
#include <cuda_bf16.h>
#include <math.h>
#include <stdint.h>

#define B_   4
#define T_   2048
#define D_   2048
#define NH   16
#define NKV  4
#define HD   128
#define KVD  (NKV*HD)      // 512
#define NQKV (D_ + 2*KVD)  // 3072
#define KW   (2*D_)        // 4096: [hi|lo] 2-plane operand width

// 1/sqrt(hd) * log2(e), folded into Q split
#define SCALE_LOG2E 0.1275174277208884f

// ---------------- scratch (__device__ globals; allocation-free rule) -------
__device__ float g_QKV[(size_t)B_ * T_ * NQKV];          // fused projection out

__device__ __nv_bfloat16 g_AE   [(size_t)(B_*T_) * KW];  // x-expand / attn-out-expand
__device__ __nv_bfloat16 g_WQKVE[(size_t)NQKV * KW];     // Wq|Wk|Wv expanded [hi|lo]
__device__ __nv_bfloat16 g_WOE  [(size_t)D_   * KW];

// attention split operands: [Qh|Ql], [Kh|Kl] (256 cols each)
__device__ __nv_bfloat16 g_Qe [(size_t)B_ * NH  * T_ * 256];
__device__ __nv_bfloat16 g_Ke [(size_t)B_ * NKV * T_ * 256];
__device__ __nv_bfloat16 g_Vth[(size_t)B_ * NKV * HD * T_];   // [b,kvh,d,t] hi
__device__ __nv_bfloat16 g_Vtl[(size_t)B_ * NKV * HD * T_];   // lo

// ---------------- helpers --------------------------------------------------
__device__ __forceinline__ uint32_t smem_u32(const void* p) {
    uint32_t a;
    asm("{ .reg .u64 t; cvta.to.shared.u64 t, %1; cvt.u32.u64 %0, t; }" : "=r"(a) : "l"(p));
    return a;
}
#define CP_ASYNC16(dst, src) \
    asm volatile("cp.async.cg.shared.global [%0], [%1], 16;" :: "r"(dst), "l"(src) : "memory")
#define CP_COMMIT() asm volatile("cp.async.commit_group;" ::: "memory")
#define CP_WAIT(N)  asm volatile("cp.async.wait_group %0;" :: "n"(N) : "memory")

#define LDMATRIX_X4(r0, r1, r2, r3, addr) \
    asm volatile("ldmatrix.sync.aligned.m8n8.x4.shared.b16 {%0,%1,%2,%3}, [%4];" \
        : "=r"(r0), "=r"(r1), "=r"(r2), "=r"(r3) : "r"(addr))

#define MMA_BF16(d, a, b0, b1) \
    asm volatile("mma.sync.aligned.m16n8k16.row.col.f32.bf16.bf16.f32 " \
        "{%0,%1,%2,%3}, {%4,%5,%6,%7}, {%8,%9}, {%0,%1,%2,%3};" \
        : "+f"((d)[0]), "+f"((d)[1]), "+f"((d)[2]), "+f"((d)[3]) \
        : "r"((a)[0]), "r"((a)[1]), "r"((a)[2]), "r"((a)[3]), "r"(b0), "r"(b1))

// pack two fp32 into bf16x2 (lo -> low half, hi -> high half)
__device__ __forceinline__ uint32_t packbf2(float lo, float hi) {
    uint32_t r;
    asm("cvt.rn.bf16x2.f32 %0, %1, %2;" : "=r"(r) : "f"(hi), "f"(lo));
    return r;
}

// ---------------------------------------------------------------------------
// split conversion: fp32 [M,K] -> bf16 [M,2K] = [hi plane | lo plane]
// ---------------------------------------------------------------------------
__global__ void split2_kernel(const float* __restrict__ in, __nv_bfloat16* __restrict__ out,
                              int K, size_t total)
{
    for (size_t e = (size_t)blockIdx.x * blockDim.x + threadIdx.x; e < total;
         e += (size_t)gridDim.x * blockDim.x) {
        size_t m = e / (size_t)K;
        int k = (int)(e - m * (size_t)K);
        float v = in[e];
        __nv_bfloat16 hi = __float2bfloat16(v);
        __nv_bfloat16* row = out + m * (size_t)(2 * K);
        row[k]     = hi;
        row[K + k] = __float2bfloat16(v - __bfloat162float(hi));
    }
}

// Fused weight split: Wq|Wk|Wv -> WQKVE rows, Wo -> WOE.  All K = D_.
__global__ void split2_weights_kernel(const float* __restrict__ Wq,
                                      const float* __restrict__ Wk,
                                      const float* __restrict__ Wv,
                                      const float* __restrict__ Wo)
{
    const size_t total = (size_t)(NQKV + D_) * D_;
    for (size_t e = (size_t)blockIdx.x * blockDim.x + threadIdx.x; e < total;
         e += (size_t)gridDim.x * blockDim.x) {
        size_t r = e / (size_t)D_;
        int k = (int)(e - r * (size_t)D_);
        const float* src;
        __nv_bfloat16* dst;
        if (r < D_)              { src = Wq + r * (size_t)D_ + k;
                                   dst = g_WQKVE + r * (size_t)KW; }
        else if (r < D_ + KVD)   { src = Wk + (r - D_) * (size_t)D_ + k;
                                   dst = g_WQKVE + r * (size_t)KW; }
        else if (r < NQKV)       { src = Wv + (r - D_ - KVD) * (size_t)D_ + k;
                                   dst = g_WQKVE + r * (size_t)KW; }
        else                     { src = Wo + (r - NQKV) * (size_t)D_ + k;
                                   dst = g_WOE + (r - NQKV) * (size_t)KW; }
        float v = *src;
        __nv_bfloat16 hi = __float2bfloat16(v);
        dst[k]      = hi;
        dst[D_ + k] = __float2bfloat16(v - __bfloat162float(hi));
    }
}

// ---------------------------------------------------------------------------
// Plane-reuse HMMA GEMM (exact R13/R11 winner: 128x128, 2-stage k32, 2 CTA/SM)
// ---------------------------------------------------------------------------
#define G2_STRIDE   80
#define G2_TILE_B   (128 * G2_STRIDE)
#define G2_STAGE_B  (4 * G2_TILE_B)
#define GEMM2_SMEM  (2 * G2_STAGE_B)
#define G2_NCH      (D_ / 32)

__global__ __launch_bounds__(256, 2)
void gemm2_bf16_nt(const __nv_bfloat16* __restrict__ A, const __nv_bfloat16* __restrict__ B,
                   float* __restrict__ C, int N)
{
    extern __shared__ char smraw[];
    const uint32_t smem = smem_u32(smraw);

    const int tid    = threadIdx.x;
    const int lane   = tid & 31;
    const int wid    = tid >> 5;
    const int warp_m = wid & 3;
    const int warp_n = wid >> 2;

    const __nv_bfloat16* Ag = A + (size_t)blockIdx.y * 128 * KW;
    const __nv_bfloat16* Bg = B + (size_t)blockIdx.x * 128 * KW;

    auto load_stage = [&](int c, int buf) {
        const uint32_t sb = smem + buf * G2_STAGE_B;
#pragma unroll
        for (int j = 0; j < 2; j++) {
            const int p   = tid + (j << 8);
            const int row = p >> 2;
            const int c16 = p & 3;
            const uint32_t off = (uint32_t)(row * G2_STRIDE + c16 * 16);
            const size_t ga = (size_t)row * KW + c * 32 + c16 * 8;
            CP_ASYNC16(sb + 0 * G2_TILE_B + off, Ag + ga);
            CP_ASYNC16(sb + 1 * G2_TILE_B + off, Ag + ga + D_);
            CP_ASYNC16(sb + 2 * G2_TILE_B + off, Bg + ga);
            CP_ASYNC16(sb + 3 * G2_TILE_B + off, Bg + ga + D_);
        }
        CP_COMMIT();
    };

    float acc[2][8][4];
#pragma unroll
    for (int t = 0; t < 2; t++)
#pragma unroll
        for (int n = 0; n < 8; n++)
#pragma unroll
            for (int x = 0; x < 4; x++) acc[t][n][x] = 0.f;

    load_stage(0, 0);

    const uint32_t lm_row = (uint32_t)((lane & 15) * G2_STRIDE + (lane >> 4) * 16);
    const uint32_t a_off  = (uint32_t)(warp_m * 32 * G2_STRIDE) + lm_row;
    const uint32_t b_off  = (uint32_t)(warp_n * 64 * G2_STRIDE) + lm_row;

    for (int c = 0; c < G2_NCH; c++) {
        CP_WAIT(0);
        __syncthreads();
        if (c + 1 < G2_NCH) load_stage(c + 1, (c + 1) & 1);

        const uint32_t st = smem + (c & 1) * G2_STAGE_B;
#pragma unroll
        for (int ks = 0; ks < 2; ks++) {
            const uint32_t ko = (uint32_t)(ks * 32);
            uint32_t ah[2][4], bh[4][4];
#pragma unroll
            for (int t = 0; t < 2; t++)
                LDMATRIX_X4(ah[t][0], ah[t][1], ah[t][2], ah[t][3],
                            st + 0 * G2_TILE_B + a_off + (uint32_t)(t * 16 * G2_STRIDE) + ko);
#pragma unroll
            for (int p = 0; p < 4; p++)
                LDMATRIX_X4(bh[p][0], bh[p][1], bh[p][2], bh[p][3],
                            st + 2 * G2_TILE_B + b_off + (uint32_t)(p * 16 * G2_STRIDE) + ko);
#pragma unroll
            for (int t = 0; t < 2; t++)
#pragma unroll
                for (int p = 0; p < 4; p++) {
                    MMA_BF16(acc[t][2 * p],     ah[t], bh[p][0], bh[p][2]);
                    MMA_BF16(acc[t][2 * p + 1], ah[t], bh[p][1], bh[p][3]);
                }
            {
                uint32_t al[2][4];
#pragma unroll
                for (int t = 0; t < 2; t++)
                    LDMATRIX_X4(al[t][0], al[t][1], al[t][2], al[t][3],
                                st + 1 * G2_TILE_B + a_off + (uint32_t)(t * 16 * G2_STRIDE) + ko);
#pragma unroll
                for (int t = 0; t < 2; t++)
#pragma unroll
                    for (int p = 0; p < 4; p++) {
                        MMA_BF16(acc[t][2 * p],     al[t], bh[p][0], bh[p][2]);
                        MMA_BF16(acc[t][2 * p + 1], al[t], bh[p][1], bh[p][3]);
                    }
            }
            {
                uint32_t bl[4][4];
#pragma unroll
                for (int p = 0; p < 4; p++)
                    LDMATRIX_X4(bl[p][0], bl[p][1], bl[p][2], bl[p][3],
                                st + 3 * G2_TILE_B + b_off + (uint32_t)(p * 16 * G2_STRIDE) + ko);
#pragma unroll
                for (int t = 0; t < 2; t++)
#pragma unroll
                    for (int p = 0; p < 4; p++) {
                        MMA_BF16(acc[t][2 * p],     ah[t], bl[p][0], bl[p][2]);
                        MMA_BF16(acc[t][2 * p + 1], ah[t], bl[p][1], bl[p][3]);
                    }
            }
        }
    }

#pragma unroll
    for (int t = 0; t < 2; t++) {
        const int row0 = blockIdx.y * 128 + warp_m * 32 + t * 16 + (lane >> 2);
#pragma unroll
        for (int n = 0; n < 8; n++) {
            const int col = blockIdx.x * 128 + warp_n * 64 + n * 8 + (lane & 3) * 2;
            *(float2*)(C + (size_t)row0 * N + col) =
                make_float2(acc[t][n][0], acc[t][n][1]);
            *(float2*)(C + (size_t)(row0 + 8) * N + col) =
                make_float2(acc[t][n][2], acc[t][n][3]);
        }
    }
}

// ---------------------------------------------------------------------------
// RoPE + hi/lo split (unchanged)
// ---------------------------------------------------------------------------
__global__ void rope_split_kernel()
{
    const int t = blockIdx.x;
    const int b = blockIdx.y;
    const float LOG2_10000_OVER_64 = 0.20762050593045952f;
    const float* base = g_QKV + (size_t)(b * T_ + t) * NQKV;

    for (int idx = threadIdx.x; idx < NH * 64; idx += blockDim.x) {
        const int head = idx >> 6;
        const int i    = idx & 63;
        const float invf = exp2f(-(float)i * LOG2_10000_OVER_64);
        float s, c;
        sincosf((float)t * invf, &s, &c);
        const float* p = base + head * HD;
        float q1 = p[i], q2 = p[i + 64];
        float r1 = (q1 * c - q2 * s) * SCALE_LOG2E;
        float r2 = (q1 * s + q2 * c) * SCALE_LOG2E;
        __nv_bfloat16 h1 = __float2bfloat16(r1);
        __nv_bfloat16 h2 = __float2bfloat16(r2);
        __nv_bfloat16* row = g_Qe + ((size_t)(b * NH + head) * T_ + t) * 256;
        row[i]       = h1;  row[i + 64]  = h2;
        row[128 + i] = __float2bfloat16(r1 - __bfloat162float(h1));
        row[192 + i] = __float2bfloat16(r2 - __bfloat162float(h2));
    }
    for (int idx = threadIdx.x; idx < NKV * 64; idx += blockDim.x) {
        const int kvh = idx >> 6;
        const int i   = idx & 63;
        const float invf = exp2f(-(float)i * LOG2_10000_OVER_64);
        float s, c;
        sincosf((float)t * invf, &s, &c);
        const float* p = base + D_ + kvh * HD;
        float q1 = p[i], q2 = p[i + 64];
        float r1 = q1 * c - q2 * s;
        float r2 = q1 * s + q2 * c;
        __nv_bfloat16 h1 = __float2bfloat16(r1);
        __nv_bfloat16 h2 = __float2bfloat16(r2);
        __nv_bfloat16* row = g_Ke + ((size_t)(b * NKV + kvh) * T_ + t) * 256;
        row[i]       = h1;  row[i + 64]  = h2;
        row[128 + i] = __float2bfloat16(r1 - __bfloat162float(h1));
        row[192 + i] = __float2bfloat16(r2 - __bfloat162float(h2));
    }
}

// V transpose + split (unchanged)
__global__ void v_split_kernel()   // grid (T_/32, B_*NKV), 256 thr
{
    __shared__ float ts[32][129];
    const int t0 = blockIdx.x * 32;
    const int bz = blockIdx.y;
    const int b = bz >> 2, kvh = bz & 3;
    const float* src = g_QKV + (size_t)(b * T_ + t0) * NQKV + D_ + KVD + kvh * HD;
#pragma unroll
    for (int k = 0; k < 16; k++) {
        const int idx = threadIdx.x + k * 256;
        const int d = idx & 127, t = idx >> 7;
        ts[t][d] = src[(size_t)t * NQKV + d];
    }
    __syncthreads();
    __nv_bfloat16* dh = g_Vth + (size_t)bz * HD * T_ + t0;
    __nv_bfloat16* dl = g_Vtl + (size_t)bz * HD * T_ + t0;
#pragma unroll
    for (int k = 0; k < 16; k++) {
        const int idx = threadIdx.x + k * 256;
        const int t = idx & 31, d = idx >> 5;
        const float v = ts[t][d];
        __nv_bfloat16 hi = __float2bfloat16(v);
        dh[(size_t)d * T_ + t] = hi;
        dl[(size_t)d * T_ + t] = __float2bfloat16(v - __bfloat162float(hi));
    }
}

// ---------------------------------------------------------------------------
// HMMA flash attention, 64-row Q tiles, 128 threads, 2 CTAs/SM.
// Same per-warp math as R13 (warp = 16 rows x 128 cols, register-resident P);
// halved CTA gives co-residency so one CTA's softmax bubble is covered by the
// other CTA's MMAs.  smem: Q 64x528 + 4 x 18KB KV buffers = 105KB.
// ---------------------------------------------------------------------------
#define AT_QROWB 528
#define AT_CH_B  18432
#define SQ_OFF   0
#define SKV_OFF  (64 * AT_QROWB)                   // 33792
#define ATT_SMEM (SKV_OFF + 4 * AT_CH_B)           // 107520

__global__ __launch_bounds__(128, 2) void attn_mma()
{
    extern __shared__ char smraw[];
    const uint32_t sb0 = smem_u32(smraw);

    const int tid  = threadIdx.x;
    const int lane = tid & 31;
    const int w    = tid >> 5;                 // 0..3
    const int qt   = 31 - (int)blockIdx.x;     // 64-row tile idx, big first
    const int h    = blockIdx.y;
    const int b    = blockIdx.z;
    const int kvh  = h >> 2;
    const int nj   = (qt + 2) >> 1;            // ceil((qt+1)/2) 128-key chunks

    const __nv_bfloat16* Qg  = g_Qe + ((size_t)(b * NH + h) * T_ + qt * 64) * 256;
    const __nv_bfloat16* Kg  = g_Ke + ((size_t)(b * NKV + kvh) * T_) * 256;
    const __nv_bfloat16* Vhg = g_Vth + (size_t)(b * NKV + kvh) * HD * T_;
    const __nv_bfloat16* Vlg = g_Vtl + (size_t)(b * NKV + kvh) * HD * T_;

    // resident Q' tile (64 x 256 bf16): 128 thr, row = tid>>1, 16 cp16 each
    {
        const int row = tid >> 1, half = tid & 1;
#pragma unroll
        for (int jj = 0; jj < 16; jj++) {
            const int c16 = half * 16 + jj;
            CP_ASYNC16(sb0 + SQ_OFF + (uint32_t)(row * AT_QROWB + c16 * 16),
                       Qg + (size_t)row * 256 + c16 * 8);
        }
        CP_COMMIT();
    }

    // K chunk c: 128 key rows x 64 bf16 (c0,c1 = Kh halves; c2,c3 = Kl halves)
    auto load_k = [&](int j, int c, int st) {
#pragma unroll
        for (int jj = 0; jj < 8; jj++) {
            const int p   = tid + (jj << 7);        // 0..1023
            const int row = p >> 3;
            const int c16 = p & 7;
            CP_ASYNC16(sb0 + SKV_OFF + st * AT_CH_B + (uint32_t)(row * 144 + c16 * 16),
                       Kg + (size_t)(j * 128 + row) * 256 + c * 64 + c16 * 8);
        }
        CP_COMMIT();
    };
    // V chunk c: 128 d rows x 64 t-cols (c0,c1 = Vh halves; c2,c3 = Vl halves)
    auto load_v = [&](int j, int c, int st) {
        const __nv_bfloat16* Vg = (c < 2) ? Vhg : Vlg;
        const int toff = j * 128 + (c & 1) * 64;
#pragma unroll
        for (int jj = 0; jj < 8; jj++) {
            const int p   = tid + (jj << 7);
            const int row = p >> 3;
            const int c16 = p & 7;
            CP_ASYNC16(sb0 + SKV_OFF + st * AT_CH_B + (uint32_t)(row * 144 + c16 * 16),
                       Vg + (size_t)row * T_ + toff + c16 * 8);
        }
        CP_COMMIT();
    };

    float o[16][4];
#pragma unroll
    for (int n = 0; n < 16; n++)
#pragma unroll
        for (int x = 0; x < 4; x++) o[n][x] = 0.f;
    float m0 = -1e30f, m1 = -1e30f, l0 = 0.f, l1 = 0.f;

    const uint32_t lm144   = (uint32_t)((lane & 15) * 144 + (lane >> 4) * 16);
    const uint32_t aq_base = sb0 + SQ_OFF + (uint32_t)((w * 16 + (lane & 15)) * AT_QROWB + (lane >> 4) * 16);
    const int rloc0 = w * 16 + (lane >> 2);    // local Q row (0..63)
    const int cbase = (lane & 3) * 2;

    load_k(0, 0, 0); load_k(0, 1, 1); load_k(0, 2, 2); load_k(0, 3, 3);

    for (int j = 0; j < nj; j++) {
        float s[16][4];
#pragma unroll
        for (int n = 0; n < 16; n++)
#pragma unroll
            for (int x = 0; x < 4; x++) s[n][x] = 0.f;

        // ================= QK phase (V(j) prefetch interleaved) ===========
#pragma unroll
        for (int c = 0; c < 4; c++) {
            if (c == 0) { CP_WAIT(3); } else { CP_WAIT(2); }
            __syncthreads();
            if (c >= 1) load_v(j, c - 1, c - 1);

            const uint32_t sbK = sb0 + SKV_OFF + c * AT_CH_B;
            const uint32_t qsl = (uint32_t)((c & 1) * 128);
#pragma unroll
            for (int ks = 0; ks < 4; ks++) {
                const uint32_t ko = (uint32_t)(ks * 32);
                uint32_t bfr[8][4];
#pragma unroll
                for (int p = 0; p < 8; p++)
                    LDMATRIX_X4(bfr[p][0], bfr[p][1], bfr[p][2], bfr[p][3],
                                sbK + (uint32_t)(p * 16 * 144) + lm144 + ko);
                uint32_t af[4];
                LDMATRIX_X4(af[0], af[1], af[2], af[3], aq_base + qsl + ko);
#pragma unroll
                for (int p = 0; p < 8; p++) {
                    MMA_BF16(s[2 * p],     af, bfr[p][0], bfr[p][2]);
                    MMA_BF16(s[2 * p + 1], af, bfr[p][1], bfr[p][3]);
                }
                if (c < 2) {
                    uint32_t ag[4];
                    LDMATRIX_X4(ag[0], ag[1], ag[2], ag[3], aq_base + qsl + 256u + ko);
#pragma unroll
                    for (int p = 0; p < 8; p++) {
                        MMA_BF16(s[2 * p],     ag, bfr[p][0], bfr[p][2]);
                        MMA_BF16(s[2 * p + 1], ag, bfr[p][1], bfr[p][3]);
                    }
                }
            }
        }
        __syncthreads();
        load_v(j, 3, 3);

        // ---- causal mask (last chunk only; global col vs global row) ----
        if (j == nj - 1) {
            const int coff = j * 128 - qt * 64;    // col offset rel. local rows
#pragma unroll
            for (int n = 0; n < 16; n++) {
                const int col = n * 8 + cbase;
#pragma unroll
                for (int x = 0; x < 4; x++) {
                    const int cc = col + (x & 1) + coff;
                    const int rr = rloc0 + ((x >> 1) << 3);
                    if (cc > rr) s[n][x] = -1e30f;
                }
            }
        }

        // ---- online softmax; pack P fragments in registers ----
        float mx0 = -1e30f, mx1 = -1e30f;
#pragma unroll
        for (int n = 0; n < 16; n++) {
            mx0 = fmaxf(mx0, fmaxf(s[n][0], s[n][1]));
            mx1 = fmaxf(mx1, fmaxf(s[n][2], s[n][3]));
        }
        mx0 = fmaxf(mx0, __shfl_xor_sync(0xffffffffu, mx0, 1));
        mx0 = fmaxf(mx0, __shfl_xor_sync(0xffffffffu, mx0, 2));
        mx1 = fmaxf(mx1, __shfl_xor_sync(0xffffffffu, mx1, 1));
        mx1 = fmaxf(mx1, __shfl_xor_sync(0xffffffffu, mx1, 2));

        const float mn0 = fmaxf(m0, mx0), mn1 = fmaxf(m1, mx1);
        const float a0 = exp2f(m0 - mn0), a1 = exp2f(m1 - mn1);
        m0 = mn0; m1 = mn1;

        uint32_t ph[8][4], pl[8][4];
        float sum0 = 0.f, sum1 = 0.f;
#pragma unroll
        for (int i = 0; i < 8; i++) {
            float p00 = exp2f(s[2*i][0]   - mn0), p01 = exp2f(s[2*i][1]   - mn0);
            float p02 = exp2f(s[2*i][2]   - mn1), p03 = exp2f(s[2*i][3]   - mn1);
            float p10 = exp2f(s[2*i+1][0] - mn0), p11 = exp2f(s[2*i+1][1] - mn0);
            float p12 = exp2f(s[2*i+1][2] - mn1), p13 = exp2f(s[2*i+1][3] - mn1);
            sum0 += p00 + p01 + p10 + p11;
            sum1 += p02 + p03 + p12 + p13;
            ph[i][0] = packbf2(p00, p01);
            ph[i][1] = packbf2(p02, p03);
            ph[i][2] = packbf2(p10, p11);
            ph[i][3] = packbf2(p12, p13);
            __nv_bfloat162 h0 = *(__nv_bfloat162*)&ph[i][0];
            __nv_bfloat162 h1 = *(__nv_bfloat162*)&ph[i][1];
            __nv_bfloat162 h2 = *(__nv_bfloat162*)&ph[i][2];
            __nv_bfloat162 h3 = *(__nv_bfloat162*)&ph[i][3];
            pl[i][0] = packbf2(p00 - __bfloat162float(h0.x), p01 - __bfloat162float(h0.y));
            pl[i][1] = packbf2(p02 - __bfloat162float(h1.x), p03 - __bfloat162float(h1.y));
            pl[i][2] = packbf2(p10 - __bfloat162float(h2.x), p11 - __bfloat162float(h2.y));
            pl[i][3] = packbf2(p12 - __bfloat162float(h3.x), p13 - __bfloat162float(h3.y));
        }
        sum0 += __shfl_xor_sync(0xffffffffu, sum0, 1);
        sum0 += __shfl_xor_sync(0xffffffffu, sum0, 2);
        sum1 += __shfl_xor_sync(0xffffffffu, sum1, 1);
        sum1 += __shfl_xor_sync(0xffffffffu, sum1, 2);
        l0 = l0 * a0 + sum0;
        l1 = l1 * a1 + sum1;

#pragma unroll
        for (int n = 0; n < 16; n++) {
            o[n][0] *= a0; o[n][1] *= a0; o[n][2] *= a1; o[n][3] *= a1;
        }

        // ================= PV phase (K(j+1) prefetch interleaved) =========
        const bool more = (j < nj - 1);
#pragma unroll
        for (int c = 0; c < 4; c++) {
            if (c == 0) { CP_WAIT(3); } else { CP_WAIT(2); }
            __syncthreads();
            if (c >= 1) { if (more) load_k(j + 1, c - 1, c - 1); else CP_COMMIT(); }

            const uint32_t sbV = sb0 + SKV_OFF + c * AT_CH_B;
            const int ib = (c & 1) * 4;
#pragma unroll
            for (int ks = 0; ks < 4; ks++) {
                uint32_t bfr[8][4];
#pragma unroll
                for (int p = 0; p < 8; p++)
                    LDMATRIX_X4(bfr[p][0], bfr[p][1], bfr[p][2], bfr[p][3],
                                sbV + (uint32_t)(p * 16 * 144) + lm144 + (uint32_t)(ks * 32));
                const int i = ib + ks;
#pragma unroll
                for (int p = 0; p < 8; p++) {
                    MMA_BF16(o[2 * p],     ph[i], bfr[p][0], bfr[p][2]);
                    MMA_BF16(o[2 * p + 1], ph[i], bfr[p][1], bfr[p][3]);
                }
                if (c < 2) {
#pragma unroll
                    for (int p = 0; p < 8; p++) {
                        MMA_BF16(o[2 * p],     pl[i], bfr[p][0], bfr[p][2]);
                        MMA_BF16(o[2 * p + 1], pl[i], bfr[p][1], bfr[p][3]);
                    }
                }
            }
        }
        __syncthreads();
        if (more) load_k(j + 1, 3, 3); else CP_COMMIT();
    }

    // ---- epilogue: normalize + [hi|lo] split straight into g_AE ----
    const float il0 = 1.f / l0, il1 = 1.f / l1;
    const int grow0 = qt * 64 + rloc0;
    __nv_bfloat16* r0 = g_AE + (size_t)(b * T_ + grow0) * KW;
    __nv_bfloat16* r1 = g_AE + (size_t)(b * T_ + grow0 + 8) * KW;
#pragma unroll
    for (int n = 0; n < 16; n++) {
        const int col = h * HD + n * 8 + cbase;
        float v0 = o[n][0] * il0, v1 = o[n][1] * il0;
        float v2 = o[n][2] * il1, v3 = o[n][3] * il1;
        __nv_bfloat16 a = __float2bfloat16(v0), bb = __float2bfloat16(v1);
        __nv_bfloat16 cc = __float2bfloat16(v2), dd = __float2bfloat16(v3);
        *(__nv_bfloat162*)(r0 + col)      = __nv_bfloat162(a, bb);
        *(__nv_bfloat162*)(r0 + D_ + col) =
            __nv_bfloat162(__float2bfloat16(v0 - __bfloat162float(a)),
                           __float2bfloat16(v1 - __bfloat162float(bb)));
        *(__nv_bfloat162*)(r1 + col)      = __nv_bfloat162(cc, dd);
        *(__nv_bfloat162*)(r1 + D_ + col) =
            __nv_bfloat162(__float2bfloat16(v2 - __bfloat162float(cc)),
                           __float2bfloat16(v3 - __bfloat162float(dd)));
    }
}

// ---------------------------------------------------------------------------
extern "C" void kernel_launch(void* const* d_in, const int* in_sizes, int n_in,
                              void* d_out, int out_size)
{
    const float* x  = (const float*)d_in[0];
    const float* Wq = (const float*)d_in[1];
    const float* Wk = (const float*)d_in[2];
    const float* Wv = (const float*)d_in[3];
    const float* Wo = (const float*)d_in[4];
    float* out = (float*)d_out;

    float* QKVb;
    __nv_bfloat16 *AE, *WQKVE, *WOE;
    cudaGetSymbolAddress((void**)&QKVb, g_QKV);
    cudaGetSymbolAddress((void**)&AE, g_AE);
    cudaGetSymbolAddress((void**)&WQKVE, g_WQKVE);
    cudaGetSymbolAddress((void**)&WOE, g_WOE);

    const int M = B_ * T_;  // 8192

    cudaFuncSetAttribute(gemm2_bf16_nt, cudaFuncAttributeMaxDynamicSharedMemorySize,
                         GEMM2_SMEM);
    cudaFuncSetAttribute(attn_mma, cudaFuncAttributeMaxDynamicSharedMemorySize,
                         ATT_SMEM);

    // split conversions: x + all four weights (fused)
    split2_kernel<<<4096, 256>>>(x, AE, D_, (size_t)M * D_);
    split2_weights_kernel<<<4096, 256>>>(Wq, Wk, Wv, Wo);

    // fused QKV projection (plane-reuse GEMM, 128x128 tiles, 2 CTA/SM)
    gemm2_bf16_nt<<<dim3(NQKV / 128, M / 128), 256, GEMM2_SMEM>>>(AE, WQKVE, QKVb, NQKV);

    // attention operand prep
    rope_split_kernel<<<dim3(T_, B_), 256>>>();
    v_split_kernel<<<dim3(T_ / 32, B_ * NKV), 256>>>();

    // tensor-core flash attention (64-row tiles, 2 CTAs/SM)
    attn_mma<<<dim3(T_ / 64, NH, B_), 128, ATT_SMEM>>>();

    // output projection
    gemm2_bf16_nt<<<dim3(D_ / 128, M / 128), 256, GEMM2_SMEM>>>(AE, WOE, out, D_);
}

// round 16
// speedup vs baseline: 1.1164x; 1.0085x over previous
#include <cuda_runtime.h>
#include <cuda_bf16.h>
#include <math.h>
#include <stdint.h>

#define B_   4
#define T_   2048
#define D_   2048
#define NH   16
#define NKV  4
#define HD   128
#define KVD  (NKV*HD)      // 512
#define NQKV (D_ + 2*KVD)  // 3072
#define KW   (2*D_)        // 4096: [hi|lo] 2-plane operand width
#define M_   (B_*T_)       // 8192

// 1/sqrt(hd) * log2(e), folded into Q split
#define SCALE_LOG2E 0.1275174277208884f

// ---------------- scratch (__device__ globals; allocation-free rule) -------
__device__ float g_QKV[(size_t)B_ * T_ * NQKV];          // fused projection out

__device__ __nv_bfloat16 g_AE   [(size_t)M_ * KW];       // x-expand / attn-out-expand
__device__ __nv_bfloat16 g_WQKVE[(size_t)NQKV * KW];     // Wq|Wk|Wv expanded [hi|lo]
__device__ __nv_bfloat16 g_WOE  [(size_t)D_   * KW];

// attention split operands: [Qh|Ql], [Kh|Kl] (256 cols each)
__device__ __nv_bfloat16 g_Qe [(size_t)B_ * NH  * T_ * 256];
__device__ __nv_bfloat16 g_Ke [(size_t)B_ * NKV * T_ * 256];
__device__ __nv_bfloat16 g_Vth[(size_t)B_ * NKV * HD * T_];   // [b,kvh,d,t] hi
__device__ __nv_bfloat16 g_Vtl[(size_t)B_ * NKV * HD * T_];   // lo

__device__ float2 g_rope_tab[T_ * 64];                   // (cos, sin) per (t, i)

// ---------------- helpers --------------------------------------------------
__device__ __forceinline__ uint32_t smem_u32(const void* p) {
    uint32_t a;
    asm("{ .reg .u64 t; cvta.to.shared.u64 t, %1; cvt.u32.u64 %0, t; }" : "=r"(a) : "l"(p));
    return a;
}
#define CP_ASYNC16(dst, src) \
    asm volatile("cp.async.cg.shared.global [%0], [%1], 16;" :: "r"(dst), "l"(src) : "memory")
#define CP_COMMIT() asm volatile("cp.async.commit_group;" ::: "memory")
#define CP_WAIT(N)  asm volatile("cp.async.wait_group %0;" :: "n"(N) : "memory")

#define LDMATRIX_X4(r0, r1, r2, r3, addr) \
    asm volatile("ldmatrix.sync.aligned.m8n8.x4.shared.b16 {%0,%1,%2,%3}, [%4];" \
        : "=r"(r0), "=r"(r1), "=r"(r2), "=r"(r3) : "r"(addr))

#define MMA_BF16(d, a, b0, b1) \
    asm volatile("mma.sync.aligned.m16n8k16.row.col.f32.bf16.bf16.f32 " \
        "{%0,%1,%2,%3}, {%4,%5,%6,%7}, {%8,%9}, {%0,%1,%2,%3};" \
        : "+f"((d)[0]), "+f"((d)[1]), "+f"((d)[2]), "+f"((d)[3]) \
        : "r"((a)[0]), "r"((a)[1]), "r"((a)[2]), "r"((a)[3]), "r"(b0), "r"(b1))

// pack two fp32 into bf16x2 (lo -> low half, hi -> high half)
__device__ __forceinline__ uint32_t packbf2(float lo, float hi) {
    uint32_t r;
    asm("cvt.rn.bf16x2.f32 %0, %1, %2;" : "=r"(r) : "f"(hi), "f"(lo));
    return r;
}

// ---------------------------------------------------------------------------
// Fused split: x -> AE, Wq|Wk|Wv -> WQKVE, Wo -> WOE (all [hi|lo] 2-plane),
// plus rope cos/sin table in trailing blocks.
// Grid: SPLIT_MAIN_BLOCKS main blocks + 64 table blocks.
// ---------------------------------------------------------------------------
#define SPLIT_MAIN_BLOCKS 8192

__global__ void split2_all_kernel(const float* __restrict__ x,
                                  const float* __restrict__ Wq,
                                  const float* __restrict__ Wk,
                                  const float* __restrict__ Wv,
                                  const float* __restrict__ Wo)
{
    if (blockIdx.x >= SPLIT_MAIN_BLOCKS) {
        // rope table: 131072 entries over 64 blocks x 256 threads
        const int tb = blockIdx.x - SPLIT_MAIN_BLOCKS;
        const float LOG2_10000_OVER_64 = 0.20762050593045952f;
        for (int e = tb * 256 + threadIdx.x; e < T_ * 64; e += 64 * 256) {
            const int t = e >> 6, i = e & 63;
            const float invf = exp2f(-(float)i * LOG2_10000_OVER_64);
            float s, c;
            sincosf((float)t * invf, &s, &c);
            g_rope_tab[e] = make_float2(c, s);
        }
        return;
    }

    const size_t total = (size_t)(M_ + NQKV + D_) * D_;
    for (size_t e = (size_t)blockIdx.x * blockDim.x + threadIdx.x; e < total;
         e += (size_t)SPLIT_MAIN_BLOCKS * blockDim.x) {
        size_t r = e / (size_t)D_;
        int k = (int)(e - r * (size_t)D_);
        const float* src;
        __nv_bfloat16* dst;
        if (r < M_)                    { src = x  + r * (size_t)D_ + k;
                                         dst = g_AE + r * (size_t)KW; }
        else if (r < M_ + D_)          { src = Wq + (r - M_) * (size_t)D_ + k;
                                         dst = g_WQKVE + (r - M_) * (size_t)KW; }
        else if (r < M_ + D_ + KVD)    { src = Wk + (r - M_ - D_) * (size_t)D_ + k;
                                         dst = g_WQKVE + (r - M_) * (size_t)KW; }
        else if (r < M_ + NQKV)        { src = Wv + (r - M_ - D_ - KVD) * (size_t)D_ + k;
                                         dst = g_WQKVE + (r - M_) * (size_t)KW; }
        else                           { src = Wo + (r - M_ - NQKV) * (size_t)D_ + k;
                                         dst = g_WOE + (r - M_ - NQKV) * (size_t)KW; }
        float v = *src;
        __nv_bfloat16 hi = __float2bfloat16(v);
        dst[k]      = hi;
        dst[D_ + k] = __float2bfloat16(v - __bfloat162float(hi));
    }
}

// ---------------------------------------------------------------------------
// Plane-reuse HMMA GEMM (exact R13/R11 winner: 128x128, 2-stage k32, 2 CTA/SM)
// ---------------------------------------------------------------------------
#define G2_STRIDE   80
#define G2_TILE_B   (128 * G2_STRIDE)
#define G2_STAGE_B  (4 * G2_TILE_B)
#define GEMM2_SMEM  (2 * G2_STAGE_B)
#define G2_NCH      (D_ / 32)

__global__ __launch_bounds__(256, 2)
void gemm2_bf16_nt(const __nv_bfloat16* __restrict__ A, const __nv_bfloat16* __restrict__ B,
                   float* __restrict__ C, int N)
{
    extern __shared__ char smraw[];
    const uint32_t smem = smem_u32(smraw);

    const int tid    = threadIdx.x;
    const int lane   = tid & 31;
    const int wid    = tid >> 5;
    const int warp_m = wid & 3;
    const int warp_n = wid >> 2;

    const __nv_bfloat16* Ag = A + (size_t)blockIdx.y * 128 * KW;
    const __nv_bfloat16* Bg = B + (size_t)blockIdx.x * 128 * KW;

    auto load_stage = [&](int c, int buf) {
        const uint32_t sb = smem + buf * G2_STAGE_B;
#pragma unroll
        for (int j = 0; j < 2; j++) {
            const int p   = tid + (j << 8);
            const int row = p >> 2;
            const int c16 = p & 3;
            const uint32_t off = (uint32_t)(row * G2_STRIDE + c16 * 16);
            const size_t ga = (size_t)row * KW + c * 32 + c16 * 8;
            CP_ASYNC16(sb + 0 * G2_TILE_B + off, Ag + ga);
            CP_ASYNC16(sb + 1 * G2_TILE_B + off, Ag + ga + D_);
            CP_ASYNC16(sb + 2 * G2_TILE_B + off, Bg + ga);
            CP_ASYNC16(sb + 3 * G2_TILE_B + off, Bg + ga + D_);
        }
        CP_COMMIT();
    };

    float acc[2][8][4];
#pragma unroll
    for (int t = 0; t < 2; t++)
#pragma unroll
        for (int n = 0; n < 8; n++)
#pragma unroll
            for (int x = 0; x < 4; x++) acc[t][n][x] = 0.f;

    load_stage(0, 0);

    const uint32_t lm_row = (uint32_t)((lane & 15) * G2_STRIDE + (lane >> 4) * 16);
    const uint32_t a_off  = (uint32_t)(warp_m * 32 * G2_STRIDE) + lm_row;
    const uint32_t b_off  = (uint32_t)(warp_n * 64 * G2_STRIDE) + lm_row;

    for (int c = 0; c < G2_NCH; c++) {
        CP_WAIT(0);
        __syncthreads();
        if (c + 1 < G2_NCH) load_stage(c + 1, (c + 1) & 1);

        const uint32_t st = smem + (c & 1) * G2_STAGE_B;
#pragma unroll
        for (int ks = 0; ks < 2; ks++) {
            const uint32_t ko = (uint32_t)(ks * 32);
            uint32_t ah[2][4], bh[4][4];
#pragma unroll
            for (int t = 0; t < 2; t++)
                LDMATRIX_X4(ah[t][0], ah[t][1], ah[t][2], ah[t][3],
                            st + 0 * G2_TILE_B + a_off + (uint32_t)(t * 16 * G2_STRIDE) + ko);
#pragma unroll
            for (int p = 0; p < 4; p++)
                LDMATRIX_X4(bh[p][0], bh[p][1], bh[p][2], bh[p][3],
                            st + 2 * G2_TILE_B + b_off + (uint32_t)(p * 16 * G2_STRIDE) + ko);
#pragma unroll
            for (int t = 0; t < 2; t++)
#pragma unroll
                for (int p = 0; p < 4; p++) {
                    MMA_BF16(acc[t][2 * p],     ah[t], bh[p][0], bh[p][2]);
                    MMA_BF16(acc[t][2 * p + 1], ah[t], bh[p][1], bh[p][3]);
                }
            {
                uint32_t al[2][4];
#pragma unroll
                for (int t = 0; t < 2; t++)
                    LDMATRIX_X4(al[t][0], al[t][1], al[t][2], al[t][3],
                                st + 1 * G2_TILE_B + a_off + (uint32_t)(t * 16 * G2_STRIDE) + ko);
#pragma unroll
                for (int t = 0; t < 2; t++)
#pragma unroll
                    for (int p = 0; p < 4; p++) {
                        MMA_BF16(acc[t][2 * p],     al[t], bh[p][0], bh[p][2]);
                        MMA_BF16(acc[t][2 * p + 1], al[t], bh[p][1], bh[p][3]);
                    }
            }
            {
                uint32_t bl[4][4];
#pragma unroll
                for (int p = 0; p < 4; p++)
                    LDMATRIX_X4(bl[p][0], bl[p][1], bl[p][2], bl[p][3],
                                st + 3 * G2_TILE_B + b_off + (uint32_t)(p * 16 * G2_STRIDE) + ko);
#pragma unroll
                for (int t = 0; t < 2; t++)
#pragma unroll
                    for (int p = 0; p < 4; p++) {
                        MMA_BF16(acc[t][2 * p],     ah[t], bl[p][0], bl[p][2]);
                        MMA_BF16(acc[t][2 * p + 1], ah[t], bl[p][1], bl[p][3]);
                    }
            }
        }
    }

#pragma unroll
    for (int t = 0; t < 2; t++) {
        const int row0 = blockIdx.y * 128 + warp_m * 32 + t * 16 + (lane >> 2);
#pragma unroll
        for (int n = 0; n < 8; n++) {
            const int col = blockIdx.x * 128 + warp_n * 64 + n * 8 + (lane & 3) * 2;
            *(float2*)(C + (size_t)row0 * N + col) =
                make_float2(acc[t][n][0], acc[t][n][1]);
            *(float2*)(C + (size_t)(row0 + 8) * N + col) =
                make_float2(acc[t][n][2], acc[t][n][3]);
        }
    }
}

// ---------------------------------------------------------------------------
// RoPE + hi/lo split using precomputed table
// ---------------------------------------------------------------------------
__global__ void rope_split_kernel()
{
    __shared__ float2 cs_tab[64];
    const int t = blockIdx.x;
    const int b = blockIdx.y;
    const float* base = g_QKV + (size_t)(b * T_ + t) * NQKV;

    if (threadIdx.x < 64) cs_tab[threadIdx.x] = g_rope_tab[t * 64 + threadIdx.x];
    __syncthreads();

    for (int idx = threadIdx.x; idx < NH * 64; idx += blockDim.x) {
        const int head = idx >> 6;
        const int i    = idx & 63;
        const float2 cs = cs_tab[i];
        const float* p = base + head * HD;
        float q1 = p[i], q2 = p[i + 64];
        float r1 = (q1 * cs.x - q2 * cs.y) * SCALE_LOG2E;
        float r2 = (q1 * cs.y + q2 * cs.x) * SCALE_LOG2E;
        __nv_bfloat16 h1 = __float2bfloat16(r1);
        __nv_bfloat16 h2 = __float2bfloat16(r2);
        __nv_bfloat16* row = g_Qe + ((size_t)(b * NH + head) * T_ + t) * 256;
        row[i]       = h1;  row[i + 64]  = h2;
        row[128 + i] = __float2bfloat16(r1 - __bfloat162float(h1));
        row[192 + i] = __float2bfloat16(r2 - __bfloat162float(h2));
    }
    for (int idx = threadIdx.x; idx < NKV * 64; idx += blockDim.x) {
        const int kvh = idx >> 6;
        const int i   = idx & 63;
        const float2 cs = cs_tab[i];
        const float* p = base + D_ + kvh * HD;
        float q1 = p[i], q2 = p[i + 64];
        float r1 = q1 * cs.x - q2 * cs.y;
        float r2 = q1 * cs.y + q2 * cs.x;
        __nv_bfloat16 h1 = __float2bfloat16(r1);
        __nv_bfloat16 h2 = __float2bfloat16(r2);
        __nv_bfloat16* row = g_Ke + ((size_t)(b * NKV + kvh) * T_ + t) * 256;
        row[i]       = h1;  row[i + 64]  = h2;
        row[128 + i] = __float2bfloat16(r1 - __bfloat162float(h1));
        row[192 + i] = __float2bfloat16(r2 - __bfloat162float(h2));
    }
}

// V transpose + split (unchanged)
__global__ void v_split_kernel()   // grid (T_/32, B_*NKV), 256 thr
{
    __shared__ float ts[32][129];
    const int t0 = blockIdx.x * 32;
    const int bz = blockIdx.y;
    const int b = bz >> 2, kvh = bz & 3;
    const float* src = g_QKV + (size_t)(b * T_ + t0) * NQKV + D_ + KVD + kvh * HD;
#pragma unroll
    for (int k = 0; k < 16; k++) {
        const int idx = threadIdx.x + k * 256;
        const int d = idx & 127, t = idx >> 7;
        ts[t][d] = src[(size_t)t * NQKV + d];
    }
    __syncthreads();
    __nv_bfloat16* dh = g_Vth + (size_t)bz * HD * T_ + t0;
    __nv_bfloat16* dl = g_Vtl + (size_t)bz * HD * T_ + t0;
#pragma unroll
    for (int k = 0; k < 16; k++) {
        const int idx = threadIdx.x + k * 256;
        const int t = idx & 31, d = idx >> 5;
        const float v = ts[t][d];
        __nv_bfloat16 hi = __float2bfloat16(v);
        dh[(size_t)d * T_ + t] = hi;
        dl[(size_t)d * T_ + t] = __float2bfloat16(v - __bfloat162float(hi));
    }
}

// ---------------------------------------------------------------------------
// HMMA flash attention, 128-row Q tiles, 256 thr (exact R13 winner)
// ---------------------------------------------------------------------------
#define AT_QROWB 528
#define AT_CH_B  18432
#define SQ_OFF   0
#define SKV_OFF  (128 * AT_QROWB)                  // 67584
#define ATT_SMEM (SKV_OFF + 4 * AT_CH_B)           // 141312

__global__ __launch_bounds__(256, 1) void attn_mma()
{
    extern __shared__ char smraw[];
    const uint32_t sb0 = smem_u32(smraw);

    const int tid  = threadIdx.x;
    const int lane = tid & 31;
    const int w    = tid >> 5;
    const int qi   = 15 - (int)blockIdx.x;
    const int h    = blockIdx.y;
    const int b    = blockIdx.z;
    const int kvh  = h >> 2;

    const __nv_bfloat16* Qg  = g_Qe + ((size_t)(b * NH + h) * T_ + qi * 128) * 256;
    const __nv_bfloat16* Kg  = g_Ke + ((size_t)(b * NKV + kvh) * T_) * 256;
    const __nv_bfloat16* Vhg = g_Vth + (size_t)(b * NKV + kvh) * HD * T_;
    const __nv_bfloat16* Vlg = g_Vtl + (size_t)(b * NKV + kvh) * HD * T_;

    {
        const int row = tid >> 1, half = tid & 1;
#pragma unroll
        for (int jj = 0; jj < 16; jj++) {
            const int c16 = half * 16 + jj;
            CP_ASYNC16(sb0 + SQ_OFF + (uint32_t)(row * AT_QROWB + c16 * 16),
                       Qg + (size_t)row * 256 + c16 * 8);
        }
        CP_COMMIT();
    }

    auto load_k = [&](int j, int c, int st) {
#pragma unroll
        for (int jj = 0; jj < 4; jj++) {
            const int p   = tid + (jj << 8);
            const int row = p >> 3;
            const int c16 = p & 7;
            CP_ASYNC16(sb0 + SKV_OFF + st * AT_CH_B + (uint32_t)(row * 144 + c16 * 16),
                       Kg + (size_t)(j * 128 + row) * 256 + c * 64 + c16 * 8);
        }
        CP_COMMIT();
    };
    auto load_v = [&](int j, int c, int st) {
        const __nv_bfloat16* Vg = (c < 2) ? Vhg : Vlg;
        const int toff = j * 128 + (c & 1) * 64;
#pragma unroll
        for (int jj = 0; jj < 4; jj++) {
            const int p   = tid + (jj << 8);
            const int row = p >> 3;
            const int c16 = p & 7;
            CP_ASYNC16(sb0 + SKV_OFF + st * AT_CH_B + (uint32_t)(row * 144 + c16 * 16),
                       Vg + (size_t)row * T_ + toff + c16 * 8);
        }
        CP_COMMIT();
    };

    float o[16][4];
#pragma unroll
    for (int n = 0; n < 16; n++)
#pragma unroll
        for (int x = 0; x < 4; x++) o[n][x] = 0.f;
    float m0 = -1e30f, m1 = -1e30f, l0 = 0.f, l1 = 0.f;

    const uint32_t lm144   = (uint32_t)((lane & 15) * 144 + (lane >> 4) * 16);
    const uint32_t aq_base = sb0 + SQ_OFF + (uint32_t)((w * 16 + (lane & 15)) * AT_QROWB + (lane >> 4) * 16);
    const int rloc0 = w * 16 + (lane >> 2);
    const int cbase = (lane & 3) * 2;

    load_k(0, 0, 0); load_k(0, 1, 1); load_k(0, 2, 2); load_k(0, 3, 3);

    for (int j = 0; j <= qi; j++) {
        float s[16][4];
#pragma unroll
        for (int n = 0; n < 16; n++)
#pragma unroll
            for (int x = 0; x < 4; x++) s[n][x] = 0.f;

        // ================= QK phase (V(j) prefetch interleaved) ===========
#pragma unroll
        for (int c = 0; c < 4; c++) {
            if (c == 0) { CP_WAIT(3); } else { CP_WAIT(2); }
            __syncthreads();
            if (c >= 1) load_v(j, c - 1, c - 1);

            const uint32_t sbK = sb0 + SKV_OFF + c * AT_CH_B;
            const uint32_t qsl = (uint32_t)((c & 1) * 128);
#pragma unroll
            for (int ks = 0; ks < 4; ks++) {
                const uint32_t ko = (uint32_t)(ks * 32);
                uint32_t bfr[8][4];
#pragma unroll
                for (int p = 0; p < 8; p++)
                    LDMATRIX_X4(bfr[p][0], bfr[p][1], bfr[p][2], bfr[p][3],
                                sbK + (uint32_t)(p * 16 * 144) + lm144 + ko);
                uint32_t af[4];
                LDMATRIX_X4(af[0], af[1], af[2], af[3], aq_base + qsl + ko);
#pragma unroll
                for (int p = 0; p < 8; p++) {
                    MMA_BF16(s[2 * p],     af, bfr[p][0], bfr[p][2]);
                    MMA_BF16(s[2 * p + 1], af, bfr[p][1], bfr[p][3]);
                }
                if (c < 2) {
                    uint32_t ag[4];
                    LDMATRIX_X4(ag[0], ag[1], ag[2], ag[3], aq_base + qsl + 256u + ko);
#pragma unroll
                    for (int p = 0; p < 8; p++) {
                        MMA_BF16(s[2 * p],     ag, bfr[p][0], bfr[p][2]);
                        MMA_BF16(s[2 * p + 1], ag, bfr[p][1], bfr[p][3]);
                    }
                }
            }
        }
        __syncthreads();
        load_v(j, 3, 3);

        // ---- causal mask (diagonal block) ----
        if (j == qi) {
#pragma unroll
            for (int n = 0; n < 16; n++) {
                const int col = n * 8 + cbase;
#pragma unroll
                for (int x = 0; x < 4; x++) {
                    const int cc = col + (x & 1);
                    const int rr = rloc0 + ((x >> 1) << 3);
                    if (cc > rr) s[n][x] = -1e30f;
                }
            }
        }

        // ---- online softmax; pack P fragments in registers ----
        float mx0 = -1e30f, mx1 = -1e30f;
#pragma unroll
        for (int n = 0; n < 16; n++) {
            mx0 = fmaxf(mx0, fmaxf(s[n][0], s[n][1]));
            mx1 = fmaxf(mx1, fmaxf(s[n][2], s[n][3]));
        }
        mx0 = fmaxf(mx0, __shfl_xor_sync(0xffffffffu, mx0, 1));
        mx0 = fmaxf(mx0, __shfl_xor_sync(0xffffffffu, mx0, 2));
        mx1 = fmaxf(mx1, __shfl_xor_sync(0xffffffffu, mx1, 1));
        mx1 = fmaxf(mx1, __shfl_xor_sync(0xffffffffu, mx1, 2));

        const float mn0 = fmaxf(m0, mx0), mn1 = fmaxf(m1, mx1);
        const float a0 = exp2f(m0 - mn0), a1 = exp2f(m1 - mn1);
        m0 = mn0; m1 = mn1;

        uint32_t ph[8][4], pl[8][4];
        float sum0 = 0.f, sum1 = 0.f;
#pragma unroll
        for (int i = 0; i < 8; i++) {
            float p00 = exp2f(s[2*i][0]   - mn0), p01 = exp2f(s[2*i][1]   - mn0);
            float p02 = exp2f(s[2*i][2]   - mn1), p03 = exp2f(s[2*i][3]   - mn1);
            float p10 = exp2f(s[2*i+1][0] - mn0), p11 = exp2f(s[2*i+1][1] - mn0);
            float p12 = exp2f(s[2*i+1][2] - mn1), p13 = exp2f(s[2*i+1][3] - mn1);
            sum0 += p00 + p01 + p10 + p11;
            sum1 += p02 + p03 + p12 + p13;
            ph[i][0] = packbf2(p00, p01);
            ph[i][1] = packbf2(p02, p03);
            ph[i][2] = packbf2(p10, p11);
            ph[i][3] = packbf2(p12, p13);
            __nv_bfloat162 h0 = *(__nv_bfloat162*)&ph[i][0];
            __nv_bfloat162 h1 = *(__nv_bfloat162*)&ph[i][1];
            __nv_bfloat162 h2 = *(__nv_bfloat162*)&ph[i][2];
            __nv_bfloat162 h3 = *(__nv_bfloat162*)&ph[i][3];
            pl[i][0] = packbf2(p00 - __bfloat162float(h0.x), p01 - __bfloat162float(h0.y));
            pl[i][1] = packbf2(p02 - __bfloat162float(h1.x), p03 - __bfloat162float(h1.y));
            pl[i][2] = packbf2(p10 - __bfloat162float(h2.x), p11 - __bfloat162float(h2.y));
            pl[i][3] = packbf2(p12 - __bfloat162float(h3.x), p13 - __bfloat162float(h3.y));
        }
        sum0 += __shfl_xor_sync(0xffffffffu, sum0, 1);
        sum0 += __shfl_xor_sync(0xffffffffu, sum0, 2);
        sum1 += __shfl_xor_sync(0xffffffffu, sum1, 1);
        sum1 += __shfl_xor_sync(0xffffffffu, sum1, 2);
        l0 = l0 * a0 + sum0;
        l1 = l1 * a1 + sum1;

#pragma unroll
        for (int n = 0; n < 16; n++) {
            o[n][0] *= a0; o[n][1] *= a0; o[n][2] *= a1; o[n][3] *= a1;
        }

        // ================= PV phase (K(j+1) prefetch interleaved) =========
        const bool more = (j < qi);
#pragma unroll
        for (int c = 0; c < 4; c++) {
            if (c == 0) { CP_WAIT(3); } else { CP_WAIT(2); }
            __syncthreads();
            if (c >= 1) { if (more) load_k(j + 1, c - 1, c - 1); else CP_COMMIT(); }

            const uint32_t sbV = sb0 + SKV_OFF + c * AT_CH_B;
            const int ib = (c & 1) * 4;
#pragma unroll
            for (int ks = 0; ks < 4; ks++) {
                uint32_t bfr[8][4];
#pragma unroll
                for (int p = 0; p < 8; p++)
                    LDMATRIX_X4(bfr[p][0], bfr[p][1], bfr[p][2], bfr[p][3],
                                sbV + (uint32_t)(p * 16 * 144) + lm144 + (uint32_t)(ks * 32));
                const int i = ib + ks;
#pragma unroll
                for (int p = 0; p < 8; p++) {
                    MMA_BF16(o[2 * p],     ph[i], bfr[p][0], bfr[p][2]);
                    MMA_BF16(o[2 * p + 1], ph[i], bfr[p][1], bfr[p][3]);
                }
                if (c < 2) {
#pragma unroll
                    for (int p = 0; p < 8; p++) {
                        MMA_BF16(o[2 * p],     pl[i], bfr[p][0], bfr[p][2]);
                        MMA_BF16(o[2 * p + 1], pl[i], bfr[p][1], bfr[p][3]);
                    }
                }
            }
        }
        __syncthreads();
        if (more) load_k(j + 1, 3, 3); else CP_COMMIT();
    }

    // ---- epilogue: normalize + [hi|lo] split straight into g_AE ----
    const float il0 = 1.f / l0, il1 = 1.f / l1;
    const int grow0 = qi * 128 + rloc0;
    __nv_bfloat16* r0 = g_AE + (size_t)(b * T_ + grow0) * KW;
    __nv_bfloat16* r1 = g_AE + (size_t)(b * T_ + grow0 + 8) * KW;
#pragma unroll
    for (int n = 0; n < 16; n++) {
        const int col = h * HD + n * 8 + cbase;
        float v0 = o[n][0] * il0, v1 = o[n][1] * il0;
        float v2 = o[n][2] * il1, v3 = o[n][3] * il1;
        __nv_bfloat16 a = __float2bfloat16(v0), bb = __float2bfloat16(v1);
        __nv_bfloat16 cc = __float2bfloat16(v2), dd = __float2bfloat16(v3);
        *(__nv_bfloat162*)(r0 + col)      = __nv_bfloat162(a, bb);
        *(__nv_bfloat162*)(r0 + D_ + col) =
            __nv_bfloat162(__float2bfloat16(v0 - __bfloat162float(a)),
                           __float2bfloat16(v1 - __bfloat162float(bb)));
        *(__nv_bfloat162*)(r1 + col)      = __nv_bfloat162(cc, dd);
        *(__nv_bfloat162*)(r1 + D_ + col) =
            __nv_bfloat162(__float2bfloat16(v2 - __bfloat162float(cc)),
                           __float2bfloat16(v3 - __bfloat162float(dd)));
    }
}

// ---------------------------------------------------------------------------
extern "C" void kernel_launch(void* const* d_in, const int* in_sizes, int n_in,
                              void* d_out, int out_size)
{
    const float* x  = (const float*)d_in[0];
    const float* Wq = (const float*)d_in[1];
    const float* Wk = (const float*)d_in[2];
    const float* Wv = (const float*)d_in[3];
    const float* Wo = (const float*)d_in[4];
    float* out = (float*)d_out;

    float* QKVb;
    __nv_bfloat16 *AE, *WQKVE, *WOE;
    cudaGetSymbolAddress((void**)&QKVb, g_QKV);
    cudaGetSymbolAddress((void**)&AE, g_AE);
    cudaGetSymbolAddress((void**)&WQKVE, g_WQKVE);
    cudaGetSymbolAddress((void**)&WOE, g_WOE);

    const int M = B_ * T_;  // 8192

    cudaFuncSetAttribute(gemm2_bf16_nt, cudaFuncAttributeMaxDynamicSharedMemorySize,
                         GEMM2_SMEM);
    cudaFuncSetAttribute(attn_mma, cudaFuncAttributeMaxDynamicSharedMemorySize,
                         ATT_SMEM);

    // all split conversions + rope table in ONE launch
    split2_all_kernel<<<SPLIT_MAIN_BLOCKS + 64, 256>>>(x, Wq, Wk, Wv, Wo);

    // fused QKV projection (plane-reuse GEMM, 128x128 tiles, 2 CTA/SM)
    gemm2_bf16_nt<<<dim3(NQKV / 128, M / 128), 256, GEMM2_SMEM>>>(AE, WQKVE, QKVb, NQKV);

    // attention operand prep
    rope_split_kernel<<<dim3(T_, B_), 256>>>();
    v_split_kernel<<<dim3(T_ / 32, B_ * NKV), 256>>>();

    // tensor-core flash attention (register-resident P; writes [hi|lo] into AE)
    attn_mma<<<dim3(T_ / 128, NH, B_), 256, ATT_SMEM>>>();

    // output projection
    gemm2_bf16_nt<<<dim3(D_ / 128, M / 128), 256, GEMM2_SMEM>>>(AE, WOE, out, D_);
}

// round 17
// speedup vs baseline: 1.1166x; 1.0002x over previous
#include <cuda_runtime.h>
#include <cuda_bf16.h>
#include <math.h>
#include <stdint.h>

#define B_   4
#define T_   2048
#define D_   2048
#define NH   16
#define NKV  4
#define HD   128
#define KVD  (NKV*HD)      // 512
#define NQKV (D_ + 2*KVD)  // 3072
#define KW   (2*D_)        // 4096: [hi|lo] 2-plane operand width
#define M_   (B_*T_)       // 8192

// 1/sqrt(hd) * log2(e), folded into Q split
#define SCALE_LOG2E 0.1275174277208884f

// ---------------- scratch (__device__ globals; allocation-free rule) -------
__device__ float g_QKV[(size_t)B_ * T_ * NQKV];          // fused projection out

__device__ __nv_bfloat16 g_AE   [(size_t)M_ * KW];       // x-expand / attn-out-expand
__device__ __nv_bfloat16 g_WQKVE[(size_t)NQKV * KW];     // Wq|Wk|Wv expanded [hi|lo]
__device__ __nv_bfloat16 g_WOE  [(size_t)D_   * KW];

// attention split operands: [Qh|Ql], [Kh|Kl] (256 cols each)
__device__ __nv_bfloat16 g_Qe [(size_t)B_ * NH  * T_ * 256];
__device__ __nv_bfloat16 g_Ke [(size_t)B_ * NKV * T_ * 256];
__device__ __nv_bfloat16 g_Vth[(size_t)B_ * NKV * HD * T_];   // [b,kvh,d,t] hi
__device__ __nv_bfloat16 g_Vtl[(size_t)B_ * NKV * HD * T_];   // lo

__device__ float2 g_rope_tab[T_ * 64];                   // (cos, sin) per (t, i)

// ---------------- helpers --------------------------------------------------
__device__ __forceinline__ uint32_t smem_u32(const void* p) {
    uint32_t a;
    asm("{ .reg .u64 t; cvta.to.shared.u64 t, %1; cvt.u32.u64 %0, t; }" : "=r"(a) : "l"(p));
    return a;
}
#define CP_ASYNC16(dst, src) \
    asm volatile("cp.async.cg.shared.global [%0], [%1], 16;" :: "r"(dst), "l"(src) : "memory")
#define CP_COMMIT() asm volatile("cp.async.commit_group;" ::: "memory")
#define CP_WAIT(N)  asm volatile("cp.async.wait_group %0;" :: "n"(N) : "memory")

#define LDMATRIX_X4(r0, r1, r2, r3, addr) \
    asm volatile("ldmatrix.sync.aligned.m8n8.x4.shared.b16 {%0,%1,%2,%3}, [%4];" \
        : "=r"(r0), "=r"(r1), "=r"(r2), "=r"(r3) : "r"(addr))

#define MMA_BF16(d, a, b0, b1) \
    asm volatile("mma.sync.aligned.m16n8k16.row.col.f32.bf16.bf16.f32 " \
        "{%0,%1,%2,%3}, {%4,%5,%6,%7}, {%8,%9}, {%0,%1,%2,%3};" \
        : "+f"((d)[0]), "+f"((d)[1]), "+f"((d)[2]), "+f"((d)[3]) \
        : "r"((a)[0]), "r"((a)[1]), "r"((a)[2]), "r"((a)[3]), "r"(b0), "r"(b1))

// pack two fp32 into bf16x2 (lo -> low half, hi -> high half)
__device__ __forceinline__ uint32_t packbf2(float lo, float hi) {
    uint32_t r;
    asm("cvt.rn.bf16x2.f32 %0, %1, %2;" : "=r"(r) : "f"(hi), "f"(lo));
    return r;
}

// ---------------------------------------------------------------------------
// Fused split: x -> AE, Wq|Wk|Wv -> WQKVE, Wo -> WOE (all [hi|lo] 2-plane),
// plus rope cos/sin table in trailing blocks.
// ---------------------------------------------------------------------------
#define SPLIT_MAIN_BLOCKS 8192

__global__ void split2_all_kernel(const float* __restrict__ x,
                                  const float* __restrict__ Wq,
                                  const float* __restrict__ Wk,
                                  const float* __restrict__ Wv,
                                  const float* __restrict__ Wo)
{
    if (blockIdx.x >= SPLIT_MAIN_BLOCKS) {
        const int tb = blockIdx.x - SPLIT_MAIN_BLOCKS;
        const float LOG2_10000_OVER_64 = 0.20762050593045952f;
        for (int e = tb * 256 + threadIdx.x; e < T_ * 64; e += 64 * 256) {
            const int t = e >> 6, i = e & 63;
            const float invf = exp2f(-(float)i * LOG2_10000_OVER_64);
            float s, c;
            sincosf((float)t * invf, &s, &c);
            g_rope_tab[e] = make_float2(c, s);
        }
        return;
    }

    const size_t total = (size_t)(M_ + NQKV + D_) * D_;
    for (size_t e = (size_t)blockIdx.x * blockDim.x + threadIdx.x; e < total;
         e += (size_t)SPLIT_MAIN_BLOCKS * blockDim.x) {
        size_t r = e / (size_t)D_;
        int k = (int)(e - r * (size_t)D_);
        const float* src;
        __nv_bfloat16* dst;
        if (r < M_)                    { src = x  + r * (size_t)D_ + k;
                                         dst = g_AE + r * (size_t)KW; }
        else if (r < M_ + D_)          { src = Wq + (r - M_) * (size_t)D_ + k;
                                         dst = g_WQKVE + (r - M_) * (size_t)KW; }
        else if (r < M_ + D_ + KVD)    { src = Wk + (r - M_ - D_) * (size_t)D_ + k;
                                         dst = g_WQKVE + (r - M_) * (size_t)KW; }
        else if (r < M_ + NQKV)        { src = Wv + (r - M_ - D_ - KVD) * (size_t)D_ + k;
                                         dst = g_WQKVE + (r - M_) * (size_t)KW; }
        else                           { src = Wo + (r - M_ - NQKV) * (size_t)D_ + k;
                                         dst = g_WOE + (r - M_ - NQKV) * (size_t)KW; }
        float v = *src;
        __nv_bfloat16 hi = __float2bfloat16(v);
        dst[k]      = hi;
        dst[D_ + k] = __float2bfloat16(v - __bfloat162float(hi));
    }
}

// ---------------------------------------------------------------------------
// Plane-reuse HMMA GEMM (exact R13/R11 winner: 128x128, 2-stage k32, 2 CTA/SM)
// ---------------------------------------------------------------------------
#define G2_STRIDE   80
#define G2_TILE_B   (128 * G2_STRIDE)
#define G2_STAGE_B  (4 * G2_TILE_B)
#define GEMM2_SMEM  (2 * G2_STAGE_B)
#define G2_NCH      (D_ / 32)

__global__ __launch_bounds__(256, 2)
void gemm2_bf16_nt(const __nv_bfloat16* __restrict__ A, const __nv_bfloat16* __restrict__ B,
                   float* __restrict__ C, int N)
{
    extern __shared__ char smraw[];
    const uint32_t smem = smem_u32(smraw);

    const int tid    = threadIdx.x;
    const int lane   = tid & 31;
    const int wid    = tid >> 5;
    const int warp_m = wid & 3;
    const int warp_n = wid >> 2;

    const __nv_bfloat16* Ag = A + (size_t)blockIdx.y * 128 * KW;
    const __nv_bfloat16* Bg = B + (size_t)blockIdx.x * 128 * KW;

    auto load_stage = [&](int c, int buf) {
        const uint32_t sb = smem + buf * G2_STAGE_B;
#pragma unroll
        for (int j = 0; j < 2; j++) {
            const int p   = tid + (j << 8);
            const int row = p >> 2;
            const int c16 = p & 3;
            const uint32_t off = (uint32_t)(row * G2_STRIDE + c16 * 16);
            const size_t ga = (size_t)row * KW + c * 32 + c16 * 8;
            CP_ASYNC16(sb + 0 * G2_TILE_B + off, Ag + ga);
            CP_ASYNC16(sb + 1 * G2_TILE_B + off, Ag + ga + D_);
            CP_ASYNC16(sb + 2 * G2_TILE_B + off, Bg + ga);
            CP_ASYNC16(sb + 3 * G2_TILE_B + off, Bg + ga + D_);
        }
        CP_COMMIT();
    };

    float acc[2][8][4];
#pragma unroll
    for (int t = 0; t < 2; t++)
#pragma unroll
        for (int n = 0; n < 8; n++)
#pragma unroll
            for (int x = 0; x < 4; x++) acc[t][n][x] = 0.f;

    load_stage(0, 0);

    const uint32_t lm_row = (uint32_t)((lane & 15) * G2_STRIDE + (lane >> 4) * 16);
    const uint32_t a_off  = (uint32_t)(warp_m * 32 * G2_STRIDE) + lm_row;
    const uint32_t b_off  = (uint32_t)(warp_n * 64 * G2_STRIDE) + lm_row;

    for (int c = 0; c < G2_NCH; c++) {
        CP_WAIT(0);
        __syncthreads();
        if (c + 1 < G2_NCH) load_stage(c + 1, (c + 1) & 1);

        const uint32_t st = smem + (c & 1) * G2_STAGE_B;
#pragma unroll
        for (int ks = 0; ks < 2; ks++) {
            const uint32_t ko = (uint32_t)(ks * 32);
            uint32_t ah[2][4], bh[4][4];
#pragma unroll
            for (int t = 0; t < 2; t++)
                LDMATRIX_X4(ah[t][0], ah[t][1], ah[t][2], ah[t][3],
                            st + 0 * G2_TILE_B + a_off + (uint32_t)(t * 16 * G2_STRIDE) + ko);
#pragma unroll
            for (int p = 0; p < 4; p++)
                LDMATRIX_X4(bh[p][0], bh[p][1], bh[p][2], bh[p][3],
                            st + 2 * G2_TILE_B + b_off + (uint32_t)(p * 16 * G2_STRIDE) + ko);
#pragma unroll
            for (int t = 0; t < 2; t++)
#pragma unroll
                for (int p = 0; p < 4; p++) {
                    MMA_BF16(acc[t][2 * p],     ah[t], bh[p][0], bh[p][2]);
                    MMA_BF16(acc[t][2 * p + 1], ah[t], bh[p][1], bh[p][3]);
                }
            {
                uint32_t al[2][4];
#pragma unroll
                for (int t = 0; t < 2; t++)
                    LDMATRIX_X4(al[t][0], al[t][1], al[t][2], al[t][3],
                                st + 1 * G2_TILE_B + a_off + (uint32_t)(t * 16 * G2_STRIDE) + ko);
#pragma unroll
                for (int t = 0; t < 2; t++)
#pragma unroll
                    for (int p = 0; p < 4; p++) {
                        MMA_BF16(acc[t][2 * p],     al[t], bh[p][0], bh[p][2]);
                        MMA_BF16(acc[t][2 * p + 1], al[t], bh[p][1], bh[p][3]);
                    }
            }
            {
                uint32_t bl[4][4];
#pragma unroll
                for (int p = 0; p < 4; p++)
                    LDMATRIX_X4(bl[p][0], bl[p][1], bl[p][2], bl[p][3],
                                st + 3 * G2_TILE_B + b_off + (uint32_t)(p * 16 * G2_STRIDE) + ko);
#pragma unroll
                for (int t = 0; t < 2; t++)
#pragma unroll
                    for (int p = 0; p < 4; p++) {
                        MMA_BF16(acc[t][2 * p],     ah[t], bl[p][0], bl[p][2]);
                        MMA_BF16(acc[t][2 * p + 1], ah[t], bl[p][1], bl[p][3]);
                    }
            }
        }
    }

#pragma unroll
    for (int t = 0; t < 2; t++) {
        const int row0 = blockIdx.y * 128 + warp_m * 32 + t * 16 + (lane >> 2);
#pragma unroll
        for (int n = 0; n < 8; n++) {
            const int col = blockIdx.x * 128 + warp_n * 64 + n * 8 + (lane & 3) * 2;
            *(float2*)(C + (size_t)row0 * N + col) =
                make_float2(acc[t][n][0], acc[t][n][1]);
            *(float2*)(C + (size_t)(row0 + 8) * N + col) =
                make_float2(acc[t][n][2], acc[t][n][3]);
        }
    }
}

// ---------------------------------------------------------------------------
// Fused attention prep: rope-split for Q/K (first T_*B_ blocks) and
// V transpose-split (remaining (T_/32)*B_*NKV blocks).  One launch.
// ---------------------------------------------------------------------------
#define ROPE_BLOCKS (T_ * B_)
#define VS_BLOCKS   ((T_ / 32) * B_ * NKV)

__global__ __launch_bounds__(256) void attn_prep_kernel()
{
    if (blockIdx.x < ROPE_BLOCKS) {
        // ---- rope split: one (t, b) per block ----
        __shared__ float2 cs_tab[64];
        const int t = blockIdx.x & (T_ - 1);
        const int b = blockIdx.x >> 11;       // / T_
        const float* base = g_QKV + (size_t)(b * T_ + t) * NQKV;

        if (threadIdx.x < 64) cs_tab[threadIdx.x] = g_rope_tab[t * 64 + threadIdx.x];
        __syncthreads();

        for (int idx = threadIdx.x; idx < NH * 64; idx += blockDim.x) {
            const int head = idx >> 6;
            const int i    = idx & 63;
            const float2 cs = cs_tab[i];
            const float* p = base + head * HD;
            float q1 = p[i], q2 = p[i + 64];
            float r1 = (q1 * cs.x - q2 * cs.y) * SCALE_LOG2E;
            float r2 = (q1 * cs.y + q2 * cs.x) * SCALE_LOG2E;
            __nv_bfloat16 h1 = __float2bfloat16(r1);
            __nv_bfloat16 h2 = __float2bfloat16(r2);
            __nv_bfloat16* row = g_Qe + ((size_t)(b * NH + head) * T_ + t) * 256;
            row[i]       = h1;  row[i + 64]  = h2;
            row[128 + i] = __float2bfloat16(r1 - __bfloat162float(h1));
            row[192 + i] = __float2bfloat16(r2 - __bfloat162float(h2));
        }
        for (int idx = threadIdx.x; idx < NKV * 64; idx += blockDim.x) {
            const int kvh = idx >> 6;
            const int i   = idx & 63;
            const float2 cs = cs_tab[i];
            const float* p = base + D_ + kvh * HD;
            float q1 = p[i], q2 = p[i + 64];
            float r1 = q1 * cs.x - q2 * cs.y;
            float r2 = q1 * cs.y + q2 * cs.x;
            __nv_bfloat16 h1 = __float2bfloat16(r1);
            __nv_bfloat16 h2 = __float2bfloat16(r2);
            __nv_bfloat16* row = g_Ke + ((size_t)(b * NKV + kvh) * T_ + t) * 256;
            row[i]       = h1;  row[i + 64]  = h2;
            row[128 + i] = __float2bfloat16(r1 - __bfloat162float(h1));
            row[192 + i] = __float2bfloat16(r2 - __bfloat162float(h2));
        }
    } else {
        // ---- V transpose + split: 32-token x 128-d tile per block ----
        __shared__ float ts[32][129];
        const int vb = blockIdx.x - ROPE_BLOCKS;
        const int t0 = (vb & (T_ / 32 - 1)) * 32;
        const int bz = vb >> 6;               // / (T_/32)
        const int b = bz >> 2, kvh = bz & 3;
        const float* src = g_QKV + (size_t)(b * T_ + t0) * NQKV + D_ + KVD + kvh * HD;
#pragma unroll
        for (int k = 0; k < 16; k++) {
            const int idx = threadIdx.x + k * 256;
            const int d = idx & 127, t = idx >> 7;
            ts[t][d] = src[(size_t)t * NQKV + d];
        }
        __syncthreads();
        __nv_bfloat16* dh = g_Vth + (size_t)bz * HD * T_ + t0;
        __nv_bfloat16* dl = g_Vtl + (size_t)bz * HD * T_ + t0;
#pragma unroll
        for (int k = 0; k < 16; k++) {
            const int idx = threadIdx.x + k * 256;
            const int t = idx & 31, d = idx >> 5;
            const float v = ts[t][d];
            __nv_bfloat16 hi = __float2bfloat16(v);
            dh[(size_t)d * T_ + t] = hi;
            dl[(size_t)d * T_ + t] = __float2bfloat16(v - __bfloat162float(hi));
        }
    }
}

// ---------------------------------------------------------------------------
// HMMA flash attention, 128-row Q tiles, 256 thr (exact R13/R16 winner)
// ---------------------------------------------------------------------------
#define AT_QROWB 528
#define AT_CH_B  18432
#define SQ_OFF   0
#define SKV_OFF  (128 * AT_QROWB)                  // 67584
#define ATT_SMEM (SKV_OFF + 4 * AT_CH_B)           // 141312

__global__ __launch_bounds__(256, 1) void attn_mma()
{
    extern __shared__ char smraw[];
    const uint32_t sb0 = smem_u32(smraw);

    const int tid  = threadIdx.x;
    const int lane = tid & 31;
    const int w    = tid >> 5;
    const int qi   = 15 - (int)blockIdx.x;
    const int h    = blockIdx.y;
    const int b    = blockIdx.z;
    const int kvh  = h >> 2;

    const __nv_bfloat16* Qg  = g_Qe + ((size_t)(b * NH + h) * T_ + qi * 128) * 256;
    const __nv_bfloat16* Kg  = g_Ke + ((size_t)(b * NKV + kvh) * T_) * 256;
    const __nv_bfloat16* Vhg = g_Vth + (size_t)(b * NKV + kvh) * HD * T_;
    const __nv_bfloat16* Vlg = g_Vtl + (size_t)(b * NKV + kvh) * HD * T_;

    {
        const int row = tid >> 1, half = tid & 1;
#pragma unroll
        for (int jj = 0; jj < 16; jj++) {
            const int c16 = half * 16 + jj;
            CP_ASYNC16(sb0 + SQ_OFF + (uint32_t)(row * AT_QROWB + c16 * 16),
                       Qg + (size_t)row * 256 + c16 * 8);
        }
        CP_COMMIT();
    }

    auto load_k = [&](int j, int c, int st) {
#pragma unroll
        for (int jj = 0; jj < 4; jj++) {
            const int p   = tid + (jj << 8);
            const int row = p >> 3;
            const int c16 = p & 7;
            CP_ASYNC16(sb0 + SKV_OFF + st * AT_CH_B + (uint32_t)(row * 144 + c16 * 16),
                       Kg + (size_t)(j * 128 + row) * 256 + c * 64 + c16 * 8);
        }
        CP_COMMIT();
    };
    auto load_v = [&](int j, int c, int st) {
        const __nv_bfloat16* Vg = (c < 2) ? Vhg : Vlg;
        const int toff = j * 128 + (c & 1) * 64;
#pragma unroll
        for (int jj = 0; jj < 4; jj++) {
            const int p   = tid + (jj << 8);
            const int row = p >> 3;
            const int c16 = p & 7;
            CP_ASYNC16(sb0 + SKV_OFF + st * AT_CH_B + (uint32_t)(row * 144 + c16 * 16),
                       Vg + (size_t)row * T_ + toff + c16 * 8);
        }
        CP_COMMIT();
    };

    float o[16][4];
#pragma unroll
    for (int n = 0; n < 16; n++)
#pragma unroll
        for (int x = 0; x < 4; x++) o[n][x] = 0.f;
    float m0 = -1e30f, m1 = -1e30f, l0 = 0.f, l1 = 0.f;

    const uint32_t lm144   = (uint32_t)((lane & 15) * 144 + (lane >> 4) * 16);
    const uint32_t aq_base = sb0 + SQ_OFF + (uint32_t)((w * 16 + (lane & 15)) * AT_QROWB + (lane >> 4) * 16);
    const int rloc0 = w * 16 + (lane >> 2);
    const int cbase = (lane & 3) * 2;

    load_k(0, 0, 0); load_k(0, 1, 1); load_k(0, 2, 2); load_k(0, 3, 3);

    for (int j = 0; j <= qi; j++) {
        float s[16][4];
#pragma unroll
        for (int n = 0; n < 16; n++)
#pragma unroll
            for (int x = 0; x < 4; x++) s[n][x] = 0.f;

        // ================= QK phase (V(j) prefetch interleaved) ===========
#pragma unroll
        for (int c = 0; c < 4; c++) {
            if (c == 0) { CP_WAIT(3); } else { CP_WAIT(2); }
            __syncthreads();
            if (c >= 1) load_v(j, c - 1, c - 1);

            const uint32_t sbK = sb0 + SKV_OFF + c * AT_CH_B;
            const uint32_t qsl = (uint32_t)((c & 1) * 128);
#pragma unroll
            for (int ks = 0; ks < 4; ks++) {
                const uint32_t ko = (uint32_t)(ks * 32);
                uint32_t bfr[8][4];
#pragma unroll
                for (int p = 0; p < 8; p++)
                    LDMATRIX_X4(bfr[p][0], bfr[p][1], bfr[p][2], bfr[p][3],
                                sbK + (uint32_t)(p * 16 * 144) + lm144 + ko);
                uint32_t af[4];
                LDMATRIX_X4(af[0], af[1], af[2], af[3], aq_base + qsl + ko);
#pragma unroll
                for (int p = 0; p < 8; p++) {
                    MMA_BF16(s[2 * p],     af, bfr[p][0], bfr[p][2]);
                    MMA_BF16(s[2 * p + 1], af, bfr[p][1], bfr[p][3]);
                }
                if (c < 2) {
                    uint32_t ag[4];
                    LDMATRIX_X4(ag[0], ag[1], ag[2], ag[3], aq_base + qsl + 256u + ko);
#pragma unroll
                    for (int p = 0; p < 8; p++) {
                        MMA_BF16(s[2 * p],     ag, bfr[p][0], bfr[p][2]);
                        MMA_BF16(s[2 * p + 1], ag, bfr[p][1], bfr[p][3]);
                    }
                }
            }
        }
        __syncthreads();
        load_v(j, 3, 3);

        // ---- causal mask (diagonal block) ----
        if (j == qi) {
#pragma unroll
            for (int n = 0; n < 16; n++) {
                const int col = n * 8 + cbase;
#pragma unroll
                for (int x = 0; x < 4; x++) {
                    const int cc = col + (x & 1);
                    const int rr = rloc0 + ((x >> 1) << 3);
                    if (cc > rr) s[n][x] = -1e30f;
                }
            }
        }

        // ---- online softmax; pack P fragments in registers ----
        float mx0 = -1e30f, mx1 = -1e30f;
#pragma unroll
        for (int n = 0; n < 16; n++) {
            mx0 = fmaxf(mx0, fmaxf(s[n][0], s[n][1]));
            mx1 = fmaxf(mx1, fmaxf(s[n][2], s[n][3]));
        }
        mx0 = fmaxf(mx0, __shfl_xor_sync(0xffffffffu, mx0, 1));
        mx0 = fmaxf(mx0, __shfl_xor_sync(0xffffffffu, mx0, 2));
        mx1 = fmaxf(mx1, __shfl_xor_sync(0xffffffffu, mx1, 1));
        mx1 = fmaxf(mx1, __shfl_xor_sync(0xffffffffu, mx1, 2));

        const float mn0 = fmaxf(m0, mx0), mn1 = fmaxf(m1, mx1);
        const float a0 = exp2f(m0 - mn0), a1 = exp2f(m1 - mn1);
        m0 = mn0; m1 = mn1;

        uint32_t ph[8][4], pl[8][4];
        float sum0 = 0.f, sum1 = 0.f;
#pragma unroll
        for (int i = 0; i < 8; i++) {
            float p00 = exp2f(s[2*i][0]   - mn0), p01 = exp2f(s[2*i][1]   - mn0);
            float p02 = exp2f(s[2*i][2]   - mn1), p03 = exp2f(s[2*i][3]   - mn1);
            float p10 = exp2f(s[2*i+1][0] - mn0), p11 = exp2f(s[2*i+1][1] - mn0);
            float p12 = exp2f(s[2*i+1][2] - mn1), p13 = exp2f(s[2*i+1][3] - mn1);
            sum0 += p00 + p01 + p10 + p11;
            sum1 += p02 + p03 + p12 + p13;
            ph[i][0] = packbf2(p00, p01);
            ph[i][1] = packbf2(p02, p03);
            ph[i][2] = packbf2(p10, p11);
            ph[i][3] = packbf2(p12, p13);
            __nv_bfloat162 h0 = *(__nv_bfloat162*)&ph[i][0];
            __nv_bfloat162 h1 = *(__nv_bfloat162*)&ph[i][1];
            __nv_bfloat162 h2 = *(__nv_bfloat162*)&ph[i][2];
            __nv_bfloat162 h3 = *(__nv_bfloat162*)&ph[i][3];
            pl[i][0] = packbf2(p00 - __bfloat162float(h0.x), p01 - __bfloat162float(h0.y));
            pl[i][1] = packbf2(p02 - __bfloat162float(h1.x), p03 - __bfloat162float(h1.y));
            pl[i][2] = packbf2(p10 - __bfloat162float(h2.x), p11 - __bfloat162float(h2.y));
            pl[i][3] = packbf2(p12 - __bfloat162float(h3.x), p13 - __bfloat162float(h3.y));
        }
        sum0 += __shfl_xor_sync(0xffffffffu, sum0, 1);
        sum0 += __shfl_xor_sync(0xffffffffu, sum0, 2);
        sum1 += __shfl_xor_sync(0xffffffffu, sum1, 1);
        sum1 += __shfl_xor_sync(0xffffffffu, sum1, 2);
        l0 = l0 * a0 + sum0;
        l1 = l1 * a1 + sum1;

#pragma unroll
        for (int n = 0; n < 16; n++) {
            o[n][0] *= a0; o[n][1] *= a0; o[n][2] *= a1; o[n][3] *= a1;
        }

        // ================= PV phase (K(j+1) prefetch interleaved) =========
        const bool more = (j < qi);
#pragma unroll
        for (int c = 0; c < 4; c++) {
            if (c == 0) { CP_WAIT(3); } else { CP_WAIT(2); }
            __syncthreads();
            if (c >= 1) { if (more) load_k(j + 1, c - 1, c - 1); else CP_COMMIT(); }

            const uint32_t sbV = sb0 + SKV_OFF + c * AT_CH_B;
            const int ib = (c & 1) * 4;
#pragma unroll
            for (int ks = 0; ks < 4; ks++) {
                uint32_t bfr[8][4];
#pragma unroll
                for (int p = 0; p < 8; p++)
                    LDMATRIX_X4(bfr[p][0], bfr[p][1], bfr[p][2], bfr[p][3],
                                sbV + (uint32_t)(p * 16 * 144) + lm144 + (uint32_t)(ks * 32));
                const int i = ib + ks;
#pragma unroll
                for (int p = 0; p < 8; p++) {
                    MMA_BF16(o[2 * p],     ph[i], bfr[p][0], bfr[p][2]);
                    MMA_BF16(o[2 * p + 1], ph[i], bfr[p][1], bfr[p][3]);
                }
                if (c < 2) {
#pragma unroll
                    for (int p = 0; p < 8; p++) {
                        MMA_BF16(o[2 * p],     pl[i], bfr[p][0], bfr[p][2]);
                        MMA_BF16(o[2 * p + 1], pl[i], bfr[p][1], bfr[p][3]);
                    }
                }
            }
        }
        __syncthreads();
        if (more) load_k(j + 1, 3, 3); else CP_COMMIT();
    }

    // ---- epilogue: normalize + [hi|lo] split straight into g_AE ----
    const float il0 = 1.f / l0, il1 = 1.f / l1;
    const int grow0 = qi * 128 + rloc0;
    __nv_bfloat16* r0 = g_AE + (size_t)(b * T_ + grow0) * KW;
    __nv_bfloat16* r1 = g_AE + (size_t)(b * T_ + grow0 + 8) * KW;
#pragma unroll
    for (int n = 0; n < 16; n++) {
        const int col = h * HD + n * 8 + cbase;
        float v0 = o[n][0] * il0, v1 = o[n][1] * il0;
        float v2 = o[n][2] * il1, v3 = o[n][3] * il1;
        __nv_bfloat16 a = __float2bfloat16(v0), bb = __float2bfloat16(v1);
        __nv_bfloat16 cc = __float2bfloat16(v2), dd = __float2bfloat16(v3);
        *(__nv_bfloat162*)(r0 + col)      = __nv_bfloat162(a, bb);
        *(__nv_bfloat162*)(r0 + D_ + col) =
            __nv_bfloat162(__float2bfloat16(v0 - __bfloat162float(a)),
                           __float2bfloat16(v1 - __bfloat162float(bb)));
        *(__nv_bfloat162*)(r1 + col)      = __nv_bfloat162(cc, dd);
        *(__nv_bfloat162*)(r1 + D_ + col) =
            __nv_bfloat162(__float2bfloat16(v2 - __bfloat162float(cc)),
                           __float2bfloat16(v3 - __bfloat162float(dd)));
    }
}

// ---------------------------------------------------------------------------
extern "C" void kernel_launch(void* const* d_in, const int* in_sizes, int n_in,
                              void* d_out, int out_size)
{
    const float* x  = (const float*)d_in[0];
    const float* Wq = (const float*)d_in[1];
    const float* Wk = (const float*)d_in[2];
    const float* Wv = (const float*)d_in[3];
    const float* Wo = (const float*)d_in[4];
    float* out = (float*)d_out;

    float* QKVb;
    __nv_bfloat16 *AE, *WQKVE, *WOE;
    cudaGetSymbolAddress((void**)&QKVb, g_QKV);
    cudaGetSymbolAddress((void**)&AE, g_AE);
    cudaGetSymbolAddress((void**)&WQKVE, g_WQKVE);
    cudaGetSymbolAddress((void**)&WOE, g_WOE);

    const int M = B_ * T_;  // 8192

    cudaFuncSetAttribute(gemm2_bf16_nt, cudaFuncAttributeMaxDynamicSharedMemorySize,
                         GEMM2_SMEM);
    cudaFuncSetAttribute(attn_mma, cudaFuncAttributeMaxDynamicSharedMemorySize,
                         ATT_SMEM);

    // all split conversions + rope table in ONE launch
    split2_all_kernel<<<SPLIT_MAIN_BLOCKS + 64, 256>>>(x, Wq, Wk, Wv, Wo);

    // fused QKV projection (plane-reuse GEMM, 128x128 tiles, 2 CTA/SM)
    gemm2_bf16_nt<<<dim3(NQKV / 128, M / 128), 256, GEMM2_SMEM>>>(AE, WQKVE, QKVb, NQKV);

    // attention operand prep (rope + V transpose, ONE launch)
    attn_prep_kernel<<<ROPE_BLOCKS + VS_BLOCKS, 256>>>();

    // tensor-core flash attention (register-resident P; writes [hi|lo] into AE)
    attn_mma<<<dim3(T_ / 128, NH, B_), 256, ATT_SMEM>>>();

    // output projection
    gemm2_bf16_nt<<<dim3(D_ / 128, M / 128), 256, GEMM2_SMEM>>>(AE, WOE, out, D_);
}